// round 9
// baseline (speedup 1.0000x reference)
#include <cuda_runtime.h>

#define NN   100000
#define NE   1600000
#define HID  64
#define TXT  384
#define NBATCH 1024
#define NB_SCAN 98            // ceil(NN/1024)

// ---------------- scratch (device globals; no allocation allowed) ----------
__device__ int   d_row_f[NN + 1];
__device__ int   d_row_r[NN + 1];
__device__ int   d_cur_f[NN];
__device__ int   d_cur_r[NN];
__device__ int   d_flag[NN];
__device__ int   d_fpos[NN];
__device__ int   d_front[NN];
__device__ int   d_cnt;
__device__ int2  d_e_f[NE];           // (neighbor, weight-bits) fused
__device__ int2  d_e_r[NE];
__device__ float d_x [NN * HID];
__device__ float d_nf[NN * HID];
__device__ float d_nr[NN * HID];
__device__ int   d_bsum[384];

// ---------------- f32x2 helpers ---------------------------------------------
__device__ __forceinline__ unsigned long long pack2(float lo, float hi) {
    unsigned long long r;
    asm("mov.b64 %0, {%1, %2};" : "=l"(r) : "f"(lo), "f"(hi));
    return r;
}
__device__ __forceinline__ void unpack2(unsigned long long v, float& lo, float& hi) {
    asm("mov.b64 {%0, %1}, %2;" : "=f"(lo), "=f"(hi) : "l"(v));
}
__device__ __forceinline__ void fma2(unsigned long long& d,
                                     unsigned long long a, unsigned long long b) {
    asm("fma.rn.f32x2 %0, %1, %2, %0;" : "+l"(d) : "l"(a), "l"(b));
}

// ---------------- CSR construction -----------------------------------------
__global__ void k_zero() {
    int i = blockIdx.x * blockDim.x + threadIdx.x;
    if (i < NN) { d_cur_f[i] = 0; d_cur_r[i] = 0; d_flag[i] = 0; }
}

__global__ void k_hist(const int* __restrict__ src, const int* __restrict__ dst) {
    for (int e = blockIdx.x * blockDim.x + threadIdx.x; e < NE;
         e += gridDim.x * blockDim.x) {
        atomicAdd(&d_cur_f[dst[e]], 1);
        atomicAdd(&d_cur_r[src[e]], 1);
    }
}

__device__ __forceinline__ int wscan(int x, int lane) {
#pragma unroll
    for (int o = 1; o < 32; o <<= 1) {
        int t = __shfl_up_sync(0xFFFFFFFFu, x, o);
        if (lane >= o) x += t;
    }
    return x;
}

__device__ __forceinline__ void scanA_body(const int* cnt, int* out, int which, int blk) {
    __shared__ int ws[32];
    int t = threadIdx.x, lane = t & 31, wid = t >> 5;
    int i = blk * 1024 + t;
    int v = (i < NN) ? cnt[i] : 0;
    int x = wscan(v, lane);
    if (lane == 31) ws[wid] = x;
    __syncthreads();
    if (wid == 0) ws[lane] = wscan(ws[lane], lane);
    __syncthreads();
    int off = wid ? ws[wid - 1] : 0;
    int incl = x + off;
    if (i < NN) out[i] = incl - v;
    if (t == 1023) d_bsum[which * 128 + blk] = incl;
}

// dual scan: f and r histograms in one launch (grid = 2*NB_SCAN)
__global__ void k_scanA01() {
    int which = blockIdx.x / NB_SCAN;
    int blk   = blockIdx.x % NB_SCAN;
    scanA_body(which ? d_cur_r : d_cur_f, which ? d_row_r : d_row_f, which, blk);
}
// flag scan (after k_mark)
__global__ void k_scanA2() {
    scanA_body(d_flag, d_fpos, 2, blockIdx.x);
}

__device__ __forceinline__ void scanB_body(int which) {
    __shared__ int ws[4];
    int t = threadIdx.x, lane = t & 31, wid = t >> 5;
    int v = (t < NB_SCAN) ? d_bsum[which * 128 + t] : 0;
    int x = wscan(v, lane);
    if (lane == 31) ws[wid] = x;
    __syncthreads();
    int off = 0;
    for (int w2 = 0; w2 < wid; ++w2) off += ws[w2];
    d_bsum[which * 128 + t] = x + off - v;   // exclusive
}
__global__ void k_scanB01() { scanB_body(blockIdx.x); }     // grid=2
__global__ void k_scanB2()  { scanB_body(2); }              // grid=1

// finalize both CSR row arrays in one launch (grid covers 2*NN)
__global__ void k_scanC01() {
    int g = blockIdx.x * blockDim.x + threadIdx.x;
    int which = (g >= NN) ? 1 : 0;
    int i = g - which * NN;
    if (i >= NN) return;
    int* row = which ? d_row_r : d_row_f;
    int* cur = which ? d_cur_r : d_cur_f;
    int r = row[i] + d_bsum[which * 128 + (i >> 10)];
    row[i] = r;
    cur[i] = r;
    if (i == 0) row[NN] = NE;
}

__global__ void k_fill(const int* __restrict__ src, const int* __restrict__ dst,
                       const float* __restrict__ w) {
    for (int e = blockIdx.x * blockDim.x + threadIdx.x; e < NE;
         e += gridDim.x * blockDim.x) {
        int s = src[e], d = dst[e];
        int wb = __float_as_int(w[e]);
        int p = atomicAdd(&d_cur_f[d], 1);
        d_e_f[p] = make_int2(s, wb);
        int q = atomicAdd(&d_cur_r[s], 1);
        d_e_r[q] = make_int2(d, wb);
    }
}

// ---------------- frontier: mark batch nodes + 1-hop neighbors -------------
__global__ void k_mark(const int* __restrict__ ids) {
    int w = (blockIdx.x * blockDim.x + threadIdx.x) >> 5;
    int lane = threadIdx.x & 31;
    if (w >= NBATCH) return;
    int v = ids[w];
    if (lane == 0) d_flag[v] = 1;
    int b = d_row_f[v], e = d_row_f[v + 1];
    for (int k = b + lane; k < e; k += 32) d_flag[d_e_f[k].x] = 1;
    b = d_row_r[v]; e = d_row_r[v + 1];
    for (int k = b + lane; k < e; k += 32) d_flag[d_e_r[k].x] = 1;
}

__global__ void k_compact() {
    int i = blockIdx.x * blockDim.x + threadIdx.x;
    if (i >= NN) return;
    int pos = d_fpos[i] + d_bsum[2 * 128 + (i >> 10)];
    int f = d_flag[i];
    if (f) d_front[pos] = i;
    if (i == NN - 1) d_cnt = pos + f;
}

// ---------------- encoder: x = text @ W_enc + b_enc ------------------------
// 128x64 block tile, 128 threads, 8x8 thread tile, f32x2 packed along M.
// occupancy 5 blocks/SM: 782-block grid -> 1.06 waves instead of 1.32.
__global__ __launch_bounds__(128, 5)
void k_enc2(const float* __restrict__ A, const float* __restrict__ W,
            const float* __restrict__ b) {
    __shared__ float sA[32][132];     // [k][row], padded
    __shared__ float sW[32][64];      // [k][col]

    int tid = threadIdx.x;
    int row0 = blockIdx.x * 128;
    int cb = tid & 7;                 // 8 col-blocks
    int rb = tid >> 3;                // 16 row-blocks
    int c0 = cb * 8, r0 = rb * 8;

    unsigned long long acc[4][8];
#pragma unroll
    for (int c = 0; c < 8; ++c) {
        float bv = __ldg(b + c0 + c);
        unsigned long long bp = pack2(bv, bv);
#pragma unroll
        for (int rp = 0; rp < 4; ++rp) acc[rp][c] = bp;
    }

    for (int kc = 0; kc < TXT; kc += 32) {
        // stage A tile transposed: sA[k][row]
#pragma unroll
        for (int p = 0; p < 8; ++p) {
            int lin = tid + p * 128;
            int r = lin >> 3, c4 = (lin & 7) * 4;
            int gr = row0 + r; if (gr >= NN) gr = NN - 1;
            float4 v = *(const float4*)(A + (long long)gr * TXT + kc + c4);
            sA[c4 + 0][r] = v.x; sA[c4 + 1][r] = v.y;
            sA[c4 + 2][r] = v.z; sA[c4 + 3][r] = v.w;
        }
        // stage W chunk
#pragma unroll
        for (int p = 0; p < 4; ++p) {
            int lin = tid + p * 128;
            int k = lin >> 4, cc = (lin & 15) * 4;
            *(float4*)&sW[k][cc] = *(const float4*)(W + (kc + k) * 64 + cc);
        }
        __syncthreads();

#pragma unroll
        for (int k = 0; k < 32; ++k) {
            ulonglong2 aA = *(const ulonglong2*)&sA[k][r0];
            ulonglong2 aB = *(const ulonglong2*)&sA[k][r0 + 4];
            unsigned long long a2[4] = { aA.x, aA.y, aB.x, aB.y };
            float4 w0 = *(const float4*)&sW[k][c0];
            float4 w1 = *(const float4*)&sW[k][c0 + 4];
            float wv[8] = { w0.x, w0.y, w0.z, w0.w, w1.x, w1.y, w1.z, w1.w };
#pragma unroll
            for (int c = 0; c < 8; ++c) {
                unsigned long long w2 = pack2(wv[c], wv[c]);
#pragma unroll
                for (int rp = 0; rp < 4; ++rp) fma2(acc[rp][c], a2[rp], w2);
            }
        }
        __syncthreads();
    }

    // writeback
#pragma unroll
    for (int rp = 0; rp < 4; ++rp) {
#pragma unroll
        for (int h = 0; h < 2; ++h) {
            int gr = row0 + r0 + 2 * rp + h;
            if (gr >= NN) continue;
            float v[8];
#pragma unroll
            for (int c = 0; c < 8; ++c) {
                float lo, hi; unpack2(acc[rp][c], lo, hi);
                v[c] = h ? hi : lo;
            }
            float* op = d_x + (long long)gr * HID + c0;
            *(float4*)op       = make_float4(v[0], v[1], v[2], v[3]);
            *(float4*)(op + 4) = make_float4(v[4], v[5], v[6], v[7]);
        }
    }
}

// ---------------- frontier aggregation, BOTH directions in one launch ------
__global__ void k_aggF2() {
    int M = d_cnt;
    int lane = threadIdx.x & 31;
    int w = blockIdx.x * (blockDim.x >> 5) + (threadIdx.x >> 5);
    int which = (w >= NN) ? 1 : 0;
    int idx = w - which * NN;
    if (idx >= M) return;
    int v = d_front[idx];
    const int*  row = which ? d_row_r : d_row_f;
    const int2* enb = which ? d_e_r   : d_e_f;
    float*      out = which ? d_nr    : d_nf;

    int beg = row[v], end = row[v + 1];
    float a0 = 0.f, a1 = 0.f;
#pragma unroll 4
    for (int e = beg; e < end; ++e) {
        int2 ed = enb[e];
        float wv = __int_as_float(ed.y);
        float2 xv = *(const float2*)(d_x + (long long)ed.x * HID + 2 * lane);
        a0 = fmaf(wv, xv.x, a0);
        a1 = fmaf(wv, xv.y, a1);
    }
    float inv = (end > beg) ? 1.0f / (float)(end - beg) : 0.f;
    ((float2*)(out + (long long)v * HID))[lane] = make_float2(a0 * inv, a1 * inv);
}

// ---------------- layer-0 update at frontier rows only ---------------------
__global__ __launch_bounds__(256, 2)
void k_updF(const float* __restrict__ Wsf, const float* __restrict__ Wnf,
            const float* __restrict__ bf,
            const float* __restrict__ Wsr, const float* __restrict__ Wnr,
            const float* __restrict__ br) {
    int M = d_cnt;
    int row0 = blockIdx.x * 128;
    if (row0 >= M) return;

    extern __shared__ float sm[];
    float (*sW)[64][64] = (float (*)[64][64])sm;        // 4 x 64 x 64 = 64KB
    float (*sX)[132] = (float (*)[132])(sm + 4 * 4096);
    float (*sF)[132] = (float (*)[132])(sm + 4 * 4096 + 16 * 132);
    float (*sR)[132] = (float (*)[132])(sm + 4 * 4096 + 32 * 132);

    int tid = threadIdx.x;
    int cb = tid & 15;
    int rb = tid >> 4;
    int c0 = cb * 4, r0 = rb * 8;

#pragma unroll
    for (int p = 0; p < 16; ++p) {
        int lin = (tid + p * 256) * 4;
        int m = lin >> 12, rem = lin & 4095;
        const float* srcw = (m == 0) ? Wsf : (m == 1) ? Wnf : (m == 2) ? Wsr : Wnr;
        *(float4*)&sW[m][rem >> 6][rem & 63] = *(const float4*)(srcw + rem);
    }

    unsigned long long accf[4][4], accr[4][4];
#pragma unroll
    for (int c = 0; c < 4; ++c) {
        float bvf = __ldg(bf + c0 + c), bvr = __ldg(br + c0 + c);
        unsigned long long pf = pack2(bvf, bvf), pr = pack2(bvr, bvr);
#pragma unroll
        for (int rp = 0; rp < 4; ++rp) { accf[rp][c] = pf; accr[rp][c] = pr; }
    }

    for (int kc = 0; kc < HID; kc += 16) {
        __syncthreads();
#pragma unroll
        for (int p = 0; p < 2; ++p) {
            int lin = tid + p * 256;
            int r = lin >> 2, c4 = (lin & 3) * 4;
            int gi = row0 + r;
            int node = d_front[(gi < M) ? gi : (M - 1)];
            long long base = (long long)node * HID + kc + c4;
            float4 vx = *(const float4*)(d_x + base);
            float4 vf = *(const float4*)(d_nf + base);
            float4 vr = *(const float4*)(d_nr + base);
            sX[c4 + 0][r] = vx.x; sX[c4 + 1][r] = vx.y; sX[c4 + 2][r] = vx.z; sX[c4 + 3][r] = vx.w;
            sF[c4 + 0][r] = vf.x; sF[c4 + 1][r] = vf.y; sF[c4 + 2][r] = vf.z; sF[c4 + 3][r] = vf.w;
            sR[c4 + 0][r] = vr.x; sR[c4 + 1][r] = vr.y; sR[c4 + 2][r] = vr.z; sR[c4 + 3][r] = vr.w;
        }
        __syncthreads();

#pragma unroll
        for (int k = 0; k < 16; ++k) {
            int gk = kc + k;
            ulonglong2 xA = *(const ulonglong2*)&sX[k][r0];
            ulonglong2 xB = *(const ulonglong2*)&sX[k][r0 + 4];
            ulonglong2 fA = *(const ulonglong2*)&sF[k][r0];
            ulonglong2 fB = *(const ulonglong2*)&sF[k][r0 + 4];
            ulonglong2 rA = *(const ulonglong2*)&sR[k][r0];
            ulonglong2 rB = *(const ulonglong2*)&sR[k][r0 + 4];
            unsigned long long x2[4] = { xA.x, xA.y, xB.x, xB.y };
            unsigned long long f2[4] = { fA.x, fA.y, fB.x, fB.y };
            unsigned long long r2[4] = { rA.x, rA.y, rB.x, rB.y };
            float4 wsf = *(const float4*)&sW[0][gk][c0];
            float4 wnf = *(const float4*)&sW[1][gk][c0];
            float4 wsr = *(const float4*)&sW[2][gk][c0];
            float4 wnr = *(const float4*)&sW[3][gk][c0];
            float vsf[4] = { wsf.x, wsf.y, wsf.z, wsf.w };
            float vnf[4] = { wnf.x, wnf.y, wnf.z, wnf.w };
            float vsr[4] = { wsr.x, wsr.y, wsr.z, wsr.w };
            float vnr[4] = { wnr.x, wnr.y, wnr.z, wnr.w };
#pragma unroll
            for (int c = 0; c < 4; ++c) {
                unsigned long long wsf2 = pack2(vsf[c], vsf[c]);
                unsigned long long wnf2 = pack2(vnf[c], vnf[c]);
                unsigned long long wsr2 = pack2(vsr[c], vsr[c]);
                unsigned long long wnr2 = pack2(vnr[c], vnr[c]);
#pragma unroll
                for (int rp = 0; rp < 4; ++rp) {
                    fma2(accf[rp][c], x2[rp], wsf2);
                    fma2(accf[rp][c], f2[rp], wnf2);
                    fma2(accr[rp][c], x2[rp], wsr2);
                    fma2(accr[rp][c], r2[rp], wnr2);
                }
            }
        }
    }

#pragma unroll
    for (int rp = 0; rp < 4; ++rp) {
#pragma unroll
        for (int h = 0; h < 2; ++h) {
            int gi = row0 + r0 + 2 * rp + h;
            if (gi >= M) continue;
            int node = d_front[gi];
            float* xp = d_x + (long long)node * HID + c0;
            float4 xv = *(const float4*)xp;
            float vf[4], vr[4];
#pragma unroll
            for (int c = 0; c < 4; ++c) {
                float lo, hi;
                unpack2(accf[rp][c], lo, hi); vf[c] = h ? hi : lo;
                unpack2(accr[rp][c], lo, hi); vr[c] = h ? hi : lo;
            }
            xv.x += fmaxf(vf[0], 0.f) + fmaxf(vr[0], 0.f);
            xv.y += fmaxf(vf[1], 0.f) + fmaxf(vr[1], 0.f);
            xv.z += fmaxf(vf[2], 0.f) + fmaxf(vr[2], 0.f);
            xv.w += fmaxf(vf[3], 0.f) + fmaxf(vr[3], 0.f);
            *(float4*)xp = xv;
        }
    }
}

// ---------------- layer 2 fused, batch nodes only + L2-normalize -----------
__global__ void k_batch(const int* __restrict__ ids,
                        const float* __restrict__ Wsf, const float* __restrict__ Wnf,
                        const float* __restrict__ bf,
                        const float* __restrict__ Wsr, const float* __restrict__ Wnr,
                        const float* __restrict__ br,
                        float* __restrict__ out) {
    extern __shared__ float sm[];
    float *sWsf = sm, *sWnf = sm + 4096, *sWsr = sm + 8192, *sWnr = sm + 12288;
    float *sbf  = sm + 16384, *sbr = sm + 16448;
    for (int i = threadIdx.x; i < 4096; i += blockDim.x) {
        sWsf[i] = Wsf[i]; sWnf[i] = Wnf[i]; sWsr[i] = Wsr[i]; sWnr[i] = Wnr[i];
    }
    if (threadIdx.x < 64) { sbf[threadIdx.x] = bf[threadIdx.x]; sbr[threadIdx.x] = br[threadIdx.x]; }
    __syncthreads();

    int lane = threadIdx.x & 31;
    int i = blockIdx.x * (blockDim.x >> 5) + (threadIdx.x >> 5);
    if (i >= NBATCH) return;
    int v = ids[i];

    float nf0 = 0.f, nf1 = 0.f;
    int beg = d_row_f[v], end = d_row_f[v + 1];
#pragma unroll 4
    for (int e = beg; e < end; ++e) {
        int2 ed = d_e_f[e];
        float wv = __int_as_float(ed.y);
        float2 xv = *(const float2*)(d_x + (long long)ed.x * HID + 2 * lane);
        nf0 = fmaf(wv, xv.x, nf0); nf1 = fmaf(wv, xv.y, nf1);
    }
    float inv = (end > beg) ? 1.0f / (float)(end - beg) : 0.f;
    nf0 *= inv; nf1 *= inv;

    float nr0 = 0.f, nr1 = 0.f;
    beg = d_row_r[v]; end = d_row_r[v + 1];
#pragma unroll 4
    for (int e = beg; e < end; ++e) {
        int2 ed = d_e_r[e];
        float wv = __int_as_float(ed.y);
        float2 xv = *(const float2*)(d_x + (long long)ed.x * HID + 2 * lane);
        nr0 = fmaf(wv, xv.x, nr0); nr1 = fmaf(wv, xv.y, nr1);
    }
    inv = (end > beg) ? 1.0f / (float)(end - beg) : 0.f;
    nr0 *= inv; nr1 *= inv;

    float2 xv = *(const float2*)(d_x + (long long)v * HID + 2 * lane);
    float af0 = sbf[2 * lane], af1 = sbf[2 * lane + 1];
    float ar0 = sbr[2 * lane], ar1 = sbr[2 * lane + 1];

#pragma unroll 4
    for (int k2 = 0; k2 < 32; ++k2) {
        float xa = __shfl_sync(0xFFFFFFFFu, xv.x, k2);
        float xb = __shfl_sync(0xFFFFFFFFu, xv.y, k2);
        float fa = __shfl_sync(0xFFFFFFFFu, nf0, k2);
        float fb = __shfl_sync(0xFFFFFFFFu, nf1, k2);
        float ra = __shfl_sync(0xFFFFFFFFu, nr0, k2);
        float rb = __shfl_sync(0xFFFFFFFFu, nr1, k2);
        int ka = 2 * k2, kb = 2 * k2 + 1;
        float2 w;
        w = *(const float2*)(sWsf + ka * 64 + 2 * lane); af0 = fmaf(xa, w.x, af0); af1 = fmaf(xa, w.y, af1);
        w = *(const float2*)(sWsf + kb * 64 + 2 * lane); af0 = fmaf(xb, w.x, af0); af1 = fmaf(xb, w.y, af1);
        w = *(const float2*)(sWnf + ka * 64 + 2 * lane); af0 = fmaf(fa, w.x, af0); af1 = fmaf(fa, w.y, af1);
        w = *(const float2*)(sWnf + kb * 64 + 2 * lane); af0 = fmaf(fb, w.x, af0); af1 = fmaf(fb, w.y, af1);
        w = *(const float2*)(sWsr + ka * 64 + 2 * lane); ar0 = fmaf(xa, w.x, ar0); ar1 = fmaf(xa, w.y, ar1);
        w = *(const float2*)(sWsr + kb * 64 + 2 * lane); ar0 = fmaf(xb, w.x, ar0); ar1 = fmaf(xb, w.y, ar1);
        w = *(const float2*)(sWnr + ka * 64 + 2 * lane); ar0 = fmaf(ra, w.x, ar0); ar1 = fmaf(ra, w.y, ar1);
        w = *(const float2*)(sWnr + kb * 64 + 2 * lane); ar0 = fmaf(rb, w.x, ar0); ar1 = fmaf(rb, w.y, ar1);
    }
    float u0 = xv.x + fmaxf(af0, 0.f) + fmaxf(ar0, 0.f);
    float u1 = xv.y + fmaxf(af1, 0.f) + fmaxf(ar1, 0.f);
    float ss = u0 * u0 + u1 * u1;
#pragma unroll
    for (int o = 16; o > 0; o >>= 1) ss += __shfl_xor_sync(0xFFFFFFFFu, ss, o);
    float rinv = 1.0f / sqrtf(ss);
    ((float2*)(out + (long long)i * HID))[lane] = make_float2(u0 * rinv, u1 * rinv);
}

// ---------------- launch ----------------------------------------------------
extern "C" void kernel_launch(void* const* d_in, const int* in_sizes, int n_in,
                              void* d_out, int out_size) {
    const float* text = (const float*)d_in[0];
    const float* w    = (const float*)d_in[1];
    const float* Wenc = (const float*)d_in[2];
    const float* benc = (const float*)d_in[3];
    const float* Wsf  = (const float*)d_in[4];
    const float* Wnf  = (const float*)d_in[5];
    const float* bf   = (const float*)d_in[6];
    const float* Wsr  = (const float*)d_in[7];
    const float* Wnr  = (const float*)d_in[8];
    const float* br   = (const float*)d_in[9];
    const int*   src  = (const int*)d_in[10];
    const int*   dst  = (const int*)d_in[11];
    const int*   ids  = (const int*)d_in[12];
    float* out = (float*)d_out;

    const int UPD_SMEM   = (4 * 4096 + 48 * 132) * (int)sizeof(float);  // 90,880
    const int BATCH_SMEM = (4 * 4096 + 128) * (int)sizeof(float);       // 66,048

    // one-time (first, uncaptured correctness call): secondary stream + events
    static cudaStream_t s2 = 0;
    static cudaEvent_t evFork = 0, evJoin = 0;
    if (s2 == 0) {
        cudaStreamCreateWithFlags(&s2, cudaStreamNonBlocking);
        cudaEventCreateWithFlags(&evFork, cudaEventDisableTiming);
        cudaEventCreateWithFlags(&evJoin, cudaEventDisableTiming);
        cudaFuncSetAttribute(k_updF,  cudaFuncAttributeMaxDynamicSharedMemorySize, UPD_SMEM);
        cudaFuncSetAttribute(k_batch, cudaFuncAttributeMaxDynamicSharedMemorySize, BATCH_SMEM);
    }

    // fork point recorded BEFORE any main-stream work: encoder depends on
    // nothing from this graph, regardless of where its launch is issued.
    cudaEventRecord(evFork, 0);
    cudaStreamWaitEvent(s2, evFork, 0);

    // CSR build (both directions) on the main stream — launches #0..#4
    k_zero<<<(NN + 255) / 256, 256>>>();
    k_hist<<<1024, 256>>>(src, dst);
    k_scanA01<<<2 * NB_SCAN, 1024>>>();
    k_scanB01<<<2, 128>>>();
    k_scanC01<<<(2 * NN + 255) / 256, 256>>>();

    // encoder on s2 — issued as launch #5 so ncu (-s 5 -c 1) profiles it.
    // Overlap semantics unchanged: s2 only waits on evFork (top of graph).
    k_enc2<<<(NN + 127) / 128, 128, 0, s2>>>(text, Wenc, benc);
    cudaEventRecord(evJoin, s2);

    k_fill<<<1024, 256>>>(src, dst, w);

    // frontier = batch + 1-hop neighbors
    k_mark<<<NBATCH / 8, 256>>>(ids);
    k_scanA2<<<NB_SCAN, 1024>>>();
    k_scanB2<<<1, 128>>>();
    k_compact<<<(NN + 255) / 256, 256>>>();

    // join: aggregation needs both the encoder output and the CSR/frontier
    cudaStreamWaitEvent(0, evJoin, 0);

    // layer 0 restricted to frontier: both directions in ONE launch
    k_aggF2<<<2 * ((NN + 7) / 8), 256>>>();
    k_updF<<<(NN + 127) / 128, 256, UPD_SMEM>>>(Wsf, Wnf, bf, Wsr, Wnr, br);

    // layer 1: only at the 1024 output nodes (fused agg+update+norm)
    k_batch<<<NBATCH / 8, 256, BATCH_SMEM>>>(ids,
        Wsf + 4096, Wnf + 4096, bf + 64,
        Wsr + 4096, Wnr + 4096, br + 64, out);
}

// round 10
// speedup vs baseline: 1.1164x; 1.1164x over previous
#include <cuda_runtime.h>
#include <cstdint>

#define NN   100000
#define NE   1600000
#define HID  64
#define TXT  384
#define NBATCH 1024
#define NB_SCAN 98            // ceil(NN/1024)

// ---------------- scratch (device globals; no allocation allowed) ----------
__device__ int   d_row_f[NN + 1];
__device__ int   d_row_r[NN + 1];
__device__ int   d_cur_f[NN];
__device__ int   d_cur_r[NN];
__device__ int   d_flag[NN];
__device__ int   d_fpos[NN];
__device__ int   d_front[NN];
__device__ int   d_cnt;
__device__ int2  d_e_f[NE];           // (neighbor, weight-bits) fused
__device__ int2  d_e_r[NE];
__device__ float d_x [NN * HID];
__device__ float d_nf[NN * HID];
__device__ float d_nr[NN * HID];
__device__ int   d_bsum[384];

// ---------------- f32x2 helpers ---------------------------------------------
__device__ __forceinline__ unsigned long long pack2(float lo, float hi) {
    unsigned long long r;
    asm("mov.b64 %0, {%1, %2};" : "=l"(r) : "f"(lo), "f"(hi));
    return r;
}
__device__ __forceinline__ void unpack2(unsigned long long v, float& lo, float& hi) {
    asm("mov.b64 {%0, %1}, %2;" : "=f"(lo), "=f"(hi) : "l"(v));
}
__device__ __forceinline__ void fma2(unsigned long long& d,
                                     unsigned long long a, unsigned long long b) {
    asm("fma.rn.f32x2 %0, %1, %2, %0;" : "+l"(d) : "l"(a), "l"(b));
}

// ---------------- tf32 mma helpers ------------------------------------------
__device__ __forceinline__ float tf32hi(float v) {
    return __int_as_float(__float_as_int(v) & 0xFFFFE000);
}
__device__ __forceinline__ void mma_tf32(float* d, const uint32_t* a,
                                         const uint32_t* b) {
    asm volatile(
        "mma.sync.aligned.m16n8k8.row.col.f32.tf32.tf32.f32 "
        "{%0,%1,%2,%3}, {%4,%5,%6,%7}, {%8,%9}, {%0,%1,%2,%3};"
        : "+f"(d[0]), "+f"(d[1]), "+f"(d[2]), "+f"(d[3])
        : "r"(a[0]), "r"(a[1]), "r"(a[2]), "r"(a[3]), "r"(b[0]), "r"(b[1]));
}

// ---------------- CSR construction -----------------------------------------
__global__ void k_zero() {
    int i = blockIdx.x * blockDim.x + threadIdx.x;
    if (i < NN) { d_cur_f[i] = 0; d_cur_r[i] = 0; d_flag[i] = 0; }
}

__global__ void k_hist(const int* __restrict__ src, const int* __restrict__ dst) {
    for (int e = blockIdx.x * blockDim.x + threadIdx.x; e < NE;
         e += gridDim.x * blockDim.x) {
        atomicAdd(&d_cur_f[dst[e]], 1);
        atomicAdd(&d_cur_r[src[e]], 1);
    }
}

__device__ __forceinline__ int wscan(int x, int lane) {
#pragma unroll
    for (int o = 1; o < 32; o <<= 1) {
        int t = __shfl_up_sync(0xFFFFFFFFu, x, o);
        if (lane >= o) x += t;
    }
    return x;
}

__device__ __forceinline__ void scanA_body(const int* cnt, int* out, int which, int blk) {
    __shared__ int ws[32];
    int t = threadIdx.x, lane = t & 31, wid = t >> 5;
    int i = blk * 1024 + t;
    int v = (i < NN) ? cnt[i] : 0;
    int x = wscan(v, lane);
    if (lane == 31) ws[wid] = x;
    __syncthreads();
    if (wid == 0) ws[lane] = wscan(ws[lane], lane);
    __syncthreads();
    int off = wid ? ws[wid - 1] : 0;
    int incl = x + off;
    if (i < NN) out[i] = incl - v;
    if (t == 1023) d_bsum[which * 128 + blk] = incl;
}

__global__ void k_scanA01() {
    int which = blockIdx.x / NB_SCAN;
    int blk   = blockIdx.x % NB_SCAN;
    scanA_body(which ? d_cur_r : d_cur_f, which ? d_row_r : d_row_f, which, blk);
}
__global__ void k_scanA2() {
    scanA_body(d_flag, d_fpos, 2, blockIdx.x);
}

__device__ __forceinline__ void scanB_body(int which) {
    __shared__ int ws[4];
    int t = threadIdx.x, lane = t & 31, wid = t >> 5;
    int v = (t < NB_SCAN) ? d_bsum[which * 128 + t] : 0;
    int x = wscan(v, lane);
    if (lane == 31) ws[wid] = x;
    __syncthreads();
    int off = 0;
    for (int w2 = 0; w2 < wid; ++w2) off += ws[w2];
    d_bsum[which * 128 + t] = x + off - v;   // exclusive
}
__global__ void k_scanB01() { scanB_body(blockIdx.x); }     // grid=2
__global__ void k_scanB2()  { scanB_body(2); }              // grid=1

__global__ void k_scanC01() {
    int g = blockIdx.x * blockDim.x + threadIdx.x;
    int which = (g >= NN) ? 1 : 0;
    int i = g - which * NN;
    if (i >= NN) return;
    int* row = which ? d_row_r : d_row_f;
    int* cur = which ? d_cur_r : d_cur_f;
    int r = row[i] + d_bsum[which * 128 + (i >> 10)];
    row[i] = r;
    cur[i] = r;
    if (i == 0) row[NN] = NE;
}

__global__ void k_fill(const int* __restrict__ src, const int* __restrict__ dst,
                       const float* __restrict__ w) {
    for (int e = blockIdx.x * blockDim.x + threadIdx.x; e < NE;
         e += gridDim.x * blockDim.x) {
        int s = src[e], d = dst[e];
        int wb = __float_as_int(w[e]);
        int p = atomicAdd(&d_cur_f[d], 1);
        d_e_f[p] = make_int2(s, wb);
        int q = atomicAdd(&d_cur_r[s], 1);
        d_e_r[q] = make_int2(d, wb);
    }
}

// ---------------- frontier: mark batch nodes + 1-hop neighbors -------------
__global__ void k_mark(const int* __restrict__ ids) {
    int w = (blockIdx.x * blockDim.x + threadIdx.x) >> 5;
    int lane = threadIdx.x & 31;
    if (w >= NBATCH) return;
    int v = ids[w];
    if (lane == 0) d_flag[v] = 1;
    int b = d_row_f[v], e = d_row_f[v + 1];
    for (int k = b + lane; k < e; k += 32) d_flag[d_e_f[k].x] = 1;
    b = d_row_r[v]; e = d_row_r[v + 1];
    for (int k = b + lane; k < e; k += 32) d_flag[d_e_r[k].x] = 1;
}

__global__ void k_compact() {
    int i = blockIdx.x * blockDim.x + threadIdx.x;
    if (i >= NN) return;
    int pos = d_fpos[i] + d_bsum[2 * 128 + (i >> 10)];
    int f = d_flag[i];
    if (f) d_front[pos] = i;
    if (i == NN - 1) d_cnt = pos + f;
}

// ---------------- encoder: x = text @ W_enc + b_enc (tf32 mma.sync) --------
// 128x64 block tile, 128 threads (4 warps), each warp 32x64 via 2x8 m16n8k8
// tiles. hi/lo tf32 split (3 mma per tile) -> fp32-level accuracy.
#define SA_S 136
#define SW_S 72
__global__ __launch_bounds__(128, 4)
void k_encMMA(const float* __restrict__ A, const float* __restrict__ W,
              const float* __restrict__ b) {
    extern __shared__ float sm[];
    float* sAh = sm;                        // [32][136]
    float* sAl = sm + 32 * SA_S;            // [32][136]
    float* sWh = sm + 2 * 32 * SA_S;        // [32][72]
    float* sWl = sm + 2 * 32 * SA_S + 32 * SW_S;

    int tid  = threadIdx.x;
    int warp = tid >> 5, lane = tid & 31;
    int g = lane >> 2, tig = lane & 3;
    int row0 = blockIdx.x * 128;

    float acc[2][8][4];
#pragma unroll
    for (int mt = 0; mt < 2; ++mt)
#pragma unroll
        for (int nt = 0; nt < 8; ++nt)
#pragma unroll
            for (int q = 0; q < 4; ++q) acc[mt][nt][q] = 0.f;

    for (int kc = 0; kc < 12; ++kc) {
        // stage A chunk [128 rows][32 k] -> transposed hi/lo with XOR swizzle
#pragma unroll
        for (int p = 0; p < 8; ++p) {
            int lin = tid + p * 128;
            int r = lin >> 3, kq = lin & 7;
            int gr = row0 + r; if (gr >= NN) gr = NN - 1;
            float4 v = *(const float4*)(A + (long long)gr * TXT + kc * 32 + kq * 4);
            float vv[4] = { v.x, v.y, v.z, v.w };
#pragma unroll
            for (int j = 0; j < 4; ++j) {
                int k = kq * 4 + j;
                int rw = r ^ (((k >> 2) & 3) << 3);
                float hi = tf32hi(vv[j]);
                sAh[k * SA_S + rw] = hi;
                sAl[k * SA_S + rw] = vv[j] - hi;
            }
        }
        // stage W chunk [32 k][64 n] hi/lo (k-major, native layout)
#pragma unroll
        for (int p = 0; p < 4; ++p) {
            int lin = tid + p * 128;
            int k = lin >> 4, nq = lin & 15;
            float4 v = *(const float4*)(W + (long long)(kc * 32 + k) * HID + nq * 4);
            float vv[4] = { v.x, v.y, v.z, v.w };
#pragma unroll
            for (int j = 0; j < 4; ++j) {
                float hi = tf32hi(vv[j]);
                sWh[k * SW_S + nq * 4 + j] = hi;
                sWl[k * SW_S + nq * 4 + j] = vv[j] - hi;
            }
        }
        __syncthreads();

#pragma unroll
        for (int ks = 0; ks < 4; ++ks) {
            int k0 = ks * 8 + tig;
            int k1 = k0 + 4;
            int x0 = ((k0 >> 2) & 3) << 3;
            int x1 = ((k1 >> 2) & 3) << 3;
            uint32_t ah[2][4], al[2][4];
#pragma unroll
            for (int mt = 0; mt < 2; ++mt) {
                int r = warp * 32 + mt * 16 + g;
                int rA0 = r ^ x0, rB0 = (r + 8) ^ x0;
                int rA1 = r ^ x1, rB1 = (r + 8) ^ x1;
                ah[mt][0] = __float_as_uint(sAh[k0 * SA_S + rA0]);
                ah[mt][1] = __float_as_uint(sAh[k0 * SA_S + rB0]);
                ah[mt][2] = __float_as_uint(sAh[k1 * SA_S + rA1]);
                ah[mt][3] = __float_as_uint(sAh[k1 * SA_S + rB1]);
                al[mt][0] = __float_as_uint(sAl[k0 * SA_S + rA0]);
                al[mt][1] = __float_as_uint(sAl[k0 * SA_S + rB0]);
                al[mt][2] = __float_as_uint(sAl[k1 * SA_S + rA1]);
                al[mt][3] = __float_as_uint(sAl[k1 * SA_S + rB1]);
            }
#pragma unroll
            for (int nt = 0; nt < 8; ++nt) {
                int cb = nt * 8 + g;
                uint32_t bh[2], bl[2];
                bh[0] = __float_as_uint(sWh[k0 * SW_S + cb]);
                bh[1] = __float_as_uint(sWh[k1 * SW_S + cb]);
                bl[0] = __float_as_uint(sWl[k0 * SW_S + cb]);
                bl[1] = __float_as_uint(sWl[k1 * SW_S + cb]);
#pragma unroll
                for (int mt = 0; mt < 2; ++mt) {
                    mma_tf32(acc[mt][nt], ah[mt], bh);
                    mma_tf32(acc[mt][nt], ah[mt], bl);
                    mma_tf32(acc[mt][nt], al[mt], bh);
                }
            }
        }
        __syncthreads();
    }

    // epilogue: D + bias -> d_x
#pragma unroll
    for (int mt = 0; mt < 2; ++mt) {
#pragma unroll
        for (int nt = 0; nt < 8; ++nt) {
            int c = nt * 8 + 2 * tig;
            float2 bb = *(const float2*)(b + c);
            int r0 = row0 + warp * 32 + mt * 16 + g;
            if (r0 < NN) {
                float2 o = make_float2(acc[mt][nt][0] + bb.x,
                                       acc[mt][nt][1] + bb.y);
                *(float2*)(d_x + (long long)r0 * HID + c) = o;
            }
            int r1 = r0 + 8;
            if (r1 < NN) {
                float2 o = make_float2(acc[mt][nt][2] + bb.x,
                                       acc[mt][nt][3] + bb.y);
                *(float2*)(d_x + (long long)r1 * HID + c) = o;
            }
        }
    }
}

// ---------------- frontier aggregation, BOTH directions in one launch ------
__global__ void k_aggF2() {
    int M = d_cnt;
    int lane = threadIdx.x & 31;
    int w = blockIdx.x * (blockDim.x >> 5) + (threadIdx.x >> 5);
    int which = (w >= NN) ? 1 : 0;
    int idx = w - which * NN;
    if (idx >= M) return;
    int v = d_front[idx];
    const int*  row = which ? d_row_r : d_row_f;
    const int2* enb = which ? d_e_r   : d_e_f;
    float*      out = which ? d_nr    : d_nf;

    int beg = row[v], end = row[v + 1];
    float a0 = 0.f, a1 = 0.f;
#pragma unroll 4
    for (int e = beg; e < end; ++e) {
        int2 ed = enb[e];
        float wv = __int_as_float(ed.y);
        float2 xv = *(const float2*)(d_x + (long long)ed.x * HID + 2 * lane);
        a0 = fmaf(wv, xv.x, a0);
        a1 = fmaf(wv, xv.y, a1);
    }
    float inv = (end > beg) ? 1.0f / (float)(end - beg) : 0.f;
    ((float2*)(out + (long long)v * HID))[lane] = make_float2(a0 * inv, a1 * inv);
}

// ---------------- layer-0 update at frontier rows only ---------------------
__global__ __launch_bounds__(256, 2)
void k_updF(const float* __restrict__ Wsf, const float* __restrict__ Wnf,
            const float* __restrict__ bf,
            const float* __restrict__ Wsr, const float* __restrict__ Wnr,
            const float* __restrict__ br) {
    int M = d_cnt;
    int row0 = blockIdx.x * 128;
    if (row0 >= M) return;

    extern __shared__ float sm[];
    float (*sW)[64][64] = (float (*)[64][64])sm;        // 4 x 64 x 64 = 64KB
    float (*sX)[132] = (float (*)[132])(sm + 4 * 4096);
    float (*sF)[132] = (float (*)[132])(sm + 4 * 4096 + 16 * 132);
    float (*sR)[132] = (float (*)[132])(sm + 4 * 4096 + 32 * 132);

    int tid = threadIdx.x;
    int cb = tid & 15;
    int rb = tid >> 4;
    int c0 = cb * 4, r0 = rb * 8;

#pragma unroll
    for (int p = 0; p < 16; ++p) {
        int lin = (tid + p * 256) * 4;
        int m = lin >> 12, rem = lin & 4095;
        const float* srcw = (m == 0) ? Wsf : (m == 1) ? Wnf : (m == 2) ? Wsr : Wnr;
        *(float4*)&sW[m][rem >> 6][rem & 63] = *(const float4*)(srcw + rem);
    }

    unsigned long long accf[4][4], accr[4][4];
#pragma unroll
    for (int c = 0; c < 4; ++c) {
        float bvf = __ldg(bf + c0 + c), bvr = __ldg(br + c0 + c);
        unsigned long long pf = pack2(bvf, bvf), pr = pack2(bvr, bvr);
#pragma unroll
        for (int rp = 0; rp < 4; ++rp) { accf[rp][c] = pf; accr[rp][c] = pr; }
    }

    for (int kc = 0; kc < HID; kc += 16) {
        __syncthreads();
#pragma unroll
        for (int p = 0; p < 2; ++p) {
            int lin = tid + p * 256;
            int r = lin >> 2, c4 = (lin & 3) * 4;
            int gi = row0 + r;
            int node = d_front[(gi < M) ? gi : (M - 1)];
            long long base = (long long)node * HID + kc + c4;
            float4 vx = *(const float4*)(d_x + base);
            float4 vf = *(const float4*)(d_nf + base);
            float4 vr = *(const float4*)(d_nr + base);
            sX[c4 + 0][r] = vx.x; sX[c4 + 1][r] = vx.y; sX[c4 + 2][r] = vx.z; sX[c4 + 3][r] = vx.w;
            sF[c4 + 0][r] = vf.x; sF[c4 + 1][r] = vf.y; sF[c4 + 2][r] = vf.z; sF[c4 + 3][r] = vf.w;
            sR[c4 + 0][r] = vr.x; sR[c4 + 1][r] = vr.y; sR[c4 + 2][r] = vr.z; sR[c4 + 3][r] = vr.w;
        }
        __syncthreads();

#pragma unroll
        for (int k = 0; k < 16; ++k) {
            int gk = kc + k;
            ulonglong2 xA = *(const ulonglong2*)&sX[k][r0];
            ulonglong2 xB = *(const ulonglong2*)&sX[k][r0 + 4];
            ulonglong2 fA = *(const ulonglong2*)&sF[k][r0];
            ulonglong2 fB = *(const ulonglong2*)&sF[k][r0 + 4];
            ulonglong2 rA = *(const ulonglong2*)&sR[k][r0];
            ulonglong2 rB = *(const ulonglong2*)&sR[k][r0 + 4];
            unsigned long long x2[4] = { xA.x, xA.y, xB.x, xB.y };
            unsigned long long f2[4] = { fA.x, fA.y, fB.x, fB.y };
            unsigned long long r2[4] = { rA.x, rA.y, rB.x, rB.y };
            float4 wsf = *(const float4*)&sW[0][gk][c0];
            float4 wnf = *(const float4*)&sW[1][gk][c0];
            float4 wsr = *(const float4*)&sW[2][gk][c0];
            float4 wnr = *(const float4*)&sW[3][gk][c0];
            float vsf[4] = { wsf.x, wsf.y, wsf.z, wsf.w };
            float vnf[4] = { wnf.x, wnf.y, wnf.z, wnf.w };
            float vsr[4] = { wsr.x, wsr.y, wsr.z, wsr.w };
            float vnr[4] = { wnr.x, wnr.y, wnr.z, wnr.w };
#pragma unroll
            for (int c = 0; c < 4; ++c) {
                unsigned long long wsf2 = pack2(vsf[c], vsf[c]);
                unsigned long long wnf2 = pack2(vnf[c], vnf[c]);
                unsigned long long wsr2 = pack2(vsr[c], vsr[c]);
                unsigned long long wnr2 = pack2(vnr[c], vnr[c]);
#pragma unroll
                for (int rp = 0; rp < 4; ++rp) {
                    fma2(accf[rp][c], x2[rp], wsf2);
                    fma2(accf[rp][c], f2[rp], wnf2);
                    fma2(accr[rp][c], x2[rp], wsr2);
                    fma2(accr[rp][c], r2[rp], wnr2);
                }
            }
        }
    }

#pragma unroll
    for (int rp = 0; rp < 4; ++rp) {
#pragma unroll
        for (int h = 0; h < 2; ++h) {
            int gi = row0 + r0 + 2 * rp + h;
            if (gi >= M) continue;
            int node = d_front[gi];
            float* xp = d_x + (long long)node * HID + c0;
            float4 xv = *(const float4*)xp;
            float vf[4], vr[4];
#pragma unroll
            for (int c = 0; c < 4; ++c) {
                float lo, hi;
                unpack2(accf[rp][c], lo, hi); vf[c] = h ? hi : lo;
                unpack2(accr[rp][c], lo, hi); vr[c] = h ? hi : lo;
            }
            xv.x += fmaxf(vf[0], 0.f) + fmaxf(vr[0], 0.f);
            xv.y += fmaxf(vf[1], 0.f) + fmaxf(vr[1], 0.f);
            xv.z += fmaxf(vf[2], 0.f) + fmaxf(vr[2], 0.f);
            xv.w += fmaxf(vf[3], 0.f) + fmaxf(vr[3], 0.f);
            *(float4*)xp = xv;
        }
    }
}

// ---------------- layer 2 fused, batch nodes only + L2-normalize -----------
__global__ void k_batch(const int* __restrict__ ids,
                        const float* __restrict__ Wsf, const float* __restrict__ Wnf,
                        const float* __restrict__ bf,
                        const float* __restrict__ Wsr, const float* __restrict__ Wnr,
                        const float* __restrict__ br,
                        float* __restrict__ out) {
    extern __shared__ float sm[];
    float *sWsf = sm, *sWnf = sm + 4096, *sWsr = sm + 8192, *sWnr = sm + 12288;
    float *sbf  = sm + 16384, *sbr = sm + 16448;
    for (int i = threadIdx.x; i < 4096; i += blockDim.x) {
        sWsf[i] = Wsf[i]; sWnf[i] = Wnf[i]; sWsr[i] = Wsr[i]; sWnr[i] = Wnr[i];
    }
    if (threadIdx.x < 64) { sbf[threadIdx.x] = bf[threadIdx.x]; sbr[threadIdx.x] = br[threadIdx.x]; }
    __syncthreads();

    int lane = threadIdx.x & 31;
    int i = blockIdx.x * (blockDim.x >> 5) + (threadIdx.x >> 5);
    if (i >= NBATCH) return;
    int v = ids[i];

    float nf0 = 0.f, nf1 = 0.f;
    int beg = d_row_f[v], end = d_row_f[v + 1];
#pragma unroll 4
    for (int e = beg; e < end; ++e) {
        int2 ed = d_e_f[e];
        float wv = __int_as_float(ed.y);
        float2 xv = *(const float2*)(d_x + (long long)ed.x * HID + 2 * lane);
        nf0 = fmaf(wv, xv.x, nf0); nf1 = fmaf(wv, xv.y, nf1);
    }
    float inv = (end > beg) ? 1.0f / (float)(end - beg) : 0.f;
    nf0 *= inv; nf1 *= inv;

    float nr0 = 0.f, nr1 = 0.f;
    beg = d_row_r[v]; end = d_row_r[v + 1];
#pragma unroll 4
    for (int e = beg; e < end; ++e) {
        int2 ed = d_e_r[e];
        float wv = __int_as_float(ed.y);
        float2 xv = *(const float2*)(d_x + (long long)ed.x * HID + 2 * lane);
        nr0 = fmaf(wv, xv.x, nr0); nr1 = fmaf(wv, xv.y, nr1);
    }
    inv = (end > beg) ? 1.0f / (float)(end - beg) : 0.f;
    nr0 *= inv; nr1 *= inv;

    float2 xv = *(const float2*)(d_x + (long long)v * HID + 2 * lane);
    float af0 = sbf[2 * lane], af1 = sbf[2 * lane + 1];
    float ar0 = sbr[2 * lane], ar1 = sbr[2 * lane + 1];

#pragma unroll 4
    for (int k2 = 0; k2 < 32; ++k2) {
        float xa = __shfl_sync(0xFFFFFFFFu, xv.x, k2);
        float xb = __shfl_sync(0xFFFFFFFFu, xv.y, k2);
        float fa = __shfl_sync(0xFFFFFFFFu, nf0, k2);
        float fb = __shfl_sync(0xFFFFFFFFu, nf1, k2);
        float ra = __shfl_sync(0xFFFFFFFFu, nr0, k2);
        float rb = __shfl_sync(0xFFFFFFFFu, nr1, k2);
        int ka = 2 * k2, kb = 2 * k2 + 1;
        float2 w;
        w = *(const float2*)(sWsf + ka * 64 + 2 * lane); af0 = fmaf(xa, w.x, af0); af1 = fmaf(xa, w.y, af1);
        w = *(const float2*)(sWsf + kb * 64 + 2 * lane); af0 = fmaf(xb, w.x, af0); af1 = fmaf(xb, w.y, af1);
        w = *(const float2*)(sWnf + ka * 64 + 2 * lane); af0 = fmaf(fa, w.x, af0); af1 = fmaf(fa, w.y, af1);
        w = *(const float2*)(sWnf + kb * 64 + 2 * lane); af0 = fmaf(fb, w.x, af0); af1 = fmaf(fb, w.y, af1);
        w = *(const float2*)(sWsr + ka * 64 + 2 * lane); ar0 = fmaf(xa, w.x, ar0); ar1 = fmaf(xa, w.y, ar1);
        w = *(const float2*)(sWsr + kb * 64 + 2 * lane); ar0 = fmaf(xb, w.x, ar0); ar1 = fmaf(xb, w.y, ar1);
        w = *(const float2*)(sWnr + ka * 64 + 2 * lane); ar0 = fmaf(ra, w.x, ar0); ar1 = fmaf(ra, w.y, ar1);
        w = *(const float2*)(sWnr + kb * 64 + 2 * lane); ar0 = fmaf(rb, w.x, ar0); ar1 = fmaf(rb, w.y, ar1);
    }
    float u0 = xv.x + fmaxf(af0, 0.f) + fmaxf(ar0, 0.f);
    float u1 = xv.y + fmaxf(af1, 0.f) + fmaxf(ar1, 0.f);
    float ss = u0 * u0 + u1 * u1;
#pragma unroll
    for (int o = 16; o > 0; o >>= 1) ss += __shfl_xor_sync(0xFFFFFFFFu, ss, o);
    float rinv = 1.0f / sqrtf(ss);
    ((float2*)(out + (long long)i * HID))[lane] = make_float2(u0 * rinv, u1 * rinv);
}

// ---------------- launch ----------------------------------------------------
extern "C" void kernel_launch(void* const* d_in, const int* in_sizes, int n_in,
                              void* d_out, int out_size) {
    const float* text = (const float*)d_in[0];
    const float* w    = (const float*)d_in[1];
    const float* Wenc = (const float*)d_in[2];
    const float* benc = (const float*)d_in[3];
    const float* Wsf  = (const float*)d_in[4];
    const float* Wnf  = (const float*)d_in[5];
    const float* bf   = (const float*)d_in[6];
    const float* Wsr  = (const float*)d_in[7];
    const float* Wnr  = (const float*)d_in[8];
    const float* br   = (const float*)d_in[9];
    const int*   src  = (const int*)d_in[10];
    const int*   dst  = (const int*)d_in[11];
    const int*   ids  = (const int*)d_in[12];
    float* out = (float*)d_out;

    const int UPD_SMEM   = (4 * 4096 + 48 * 132) * (int)sizeof(float);  // 90,880
    const int BATCH_SMEM = (4 * 4096 + 128) * (int)sizeof(float);       // 66,048
    const int ENC_SMEM   = (2 * 32 * SA_S + 2 * 32 * SW_S) * (int)sizeof(float); // 53,248

    // one-time (first, uncaptured correctness call): secondary stream + events
    static cudaStream_t s2 = 0;
    static cudaEvent_t evFork = 0, evJoin = 0;
    if (s2 == 0) {
        cudaStreamCreateWithFlags(&s2, cudaStreamNonBlocking);
        cudaEventCreateWithFlags(&evFork, cudaEventDisableTiming);
        cudaEventCreateWithFlags(&evJoin, cudaEventDisableTiming);
        cudaFuncSetAttribute(k_updF,   cudaFuncAttributeMaxDynamicSharedMemorySize, UPD_SMEM);
        cudaFuncSetAttribute(k_batch,  cudaFuncAttributeMaxDynamicSharedMemorySize, BATCH_SMEM);
        cudaFuncSetAttribute(k_encMMA, cudaFuncAttributeMaxDynamicSharedMemorySize, ENC_SMEM);
    }

    // fork: encoder runs on s2, concurrent with CSR build on the main stream
    cudaEventRecord(evFork, 0);
    cudaStreamWaitEvent(s2, evFork, 0);
    k_encMMA<<<(NN + 127) / 128, 128, ENC_SMEM, s2>>>(text, Wenc, benc);
    cudaEventRecord(evJoin, s2);

    // CSR build (both directions) on the main stream
    k_zero<<<(NN + 255) / 256, 256>>>();
    k_hist<<<1024, 256>>>(src, dst);
    k_scanA01<<<2 * NB_SCAN, 1024>>>();
    k_scanB01<<<2, 128>>>();
    k_scanC01<<<(2 * NN + 255) / 256, 256>>>();
    k_fill<<<1024, 256>>>(src, dst, w);

    // frontier = batch + 1-hop neighbors
    k_mark<<<NBATCH / 8, 256>>>(ids);
    k_scanA2<<<NB_SCAN, 1024>>>();
    k_scanB2<<<1, 128>>>();
    k_compact<<<(NN + 255) / 256, 256>>>();

    // join: aggregation needs both the encoder output and the CSR/frontier
    cudaStreamWaitEvent(0, evJoin, 0);

    // layer 0 restricted to frontier: both directions in ONE launch
    k_aggF2<<<2 * ((NN + 7) / 8), 256>>>();
    k_updF<<<(NN + 127) / 128, 256, UPD_SMEM>>>(Wsf, Wnf, bf, Wsr, Wnr, br);

    // layer 1: only at the 1024 output nodes (fused agg+update+norm)
    k_batch<<<NBATCH / 8, 256, BATCH_SMEM>>>(ids,
        Wsf + 4096, Wnf + 4096, bf + 64,
        Wsr + 4096, Wnr + 4096, br + 64, out);
}

// round 11
// speedup vs baseline: 1.2628x; 1.1311x over previous
#include <cuda_runtime.h>
#include <cstdint>

#define NN   100000
#define NE   1600000
#define HID  64
#define TXT  384
#define NBATCH 1024
#define NB_SCAN 98            // ceil(NN/1024)
#define NBW  3125             // ceil(NN/32) bitmap words

// ---------------- scratch (device globals; no allocation allowed) ----------
__device__ int      d_row_f[NN + 1];
__device__ int      d_row_r[NN + 1];
__device__ int      d_cur_f[NN];
__device__ int      d_cur_r[NN];
__device__ int      d_flag[NN];
__device__ int      d_fpos[NN];
__device__ int      d_front[NN];
__device__ int      d_cnt;
__device__ unsigned d_bbit[NBW];      // batch bitmap
__device__ unsigned d_fbit[NBW];      // frontier bitmap
__device__ int2     d_e_f[NE];        // (neighbor, weight-bits) fused
__device__ int2     d_e_r[NE];
__device__ float    d_x [NN * HID];
__device__ float    d_nf[NN * HID];
__device__ float    d_nr[NN * HID];
__device__ int      d_bsum[384];

// ---------------- f32x2 helpers ---------------------------------------------
__device__ __forceinline__ unsigned long long pack2(float lo, float hi) {
    unsigned long long r;
    asm("mov.b64 %0, {%1, %2};" : "=l"(r) : "f"(lo), "f"(hi));
    return r;
}
__device__ __forceinline__ void unpack2(unsigned long long v, float& lo, float& hi) {
    asm("mov.b64 {%0, %1}, %2;" : "=f"(lo), "=f"(hi) : "l"(v));
}
__device__ __forceinline__ void fma2(unsigned long long& d,
                                     unsigned long long a, unsigned long long b) {
    asm("fma.rn.f32x2 %0, %1, %2, %0;" : "+l"(d) : "l"(a), "l"(b));
}
__device__ __forceinline__ bool getbit(const unsigned* bm, int v) {
    return (bm[v >> 5] >> (v & 31)) & 1u;
}

// ---------------- tf32 mma helpers ------------------------------------------
__device__ __forceinline__ float tf32hi(float v) {
    return __int_as_float(__float_as_int(v) & 0xFFFFE000);
}
__device__ __forceinline__ void mma_tf32(float* d, const uint32_t* a,
                                         const uint32_t* b) {
    asm volatile(
        "mma.sync.aligned.m16n8k8.row.col.f32.tf32.tf32.f32 "
        "{%0,%1,%2,%3}, {%4,%5,%6,%7}, {%8,%9}, {%0,%1,%2,%3};"
        : "+f"(d[0]), "+f"(d[1]), "+f"(d[2]), "+f"(d[3])
        : "r"(a[0]), "r"(a[1]), "r"(a[2]), "r"(a[3]), "r"(b[0]), "r"(b[1]));
}

// ---------------- CSR construction -----------------------------------------
__global__ void k_zero() {
    int i = blockIdx.x * blockDim.x + threadIdx.x;
    if (i < NN) { d_cur_f[i] = 0; d_cur_r[i] = 0; d_flag[i] = 0; }
    if (i < NBW) { d_bbit[i] = 0; d_fbit[i] = 0; }
}

// batch bitmap + flags (frontier includes batch nodes)
__global__ void k_bset(const int* __restrict__ ids) {
    int v = ids[threadIdx.x];
    atomicOr(&d_bbit[v >> 5], 1u << (v & 31));
    atomicOr(&d_fbit[v >> 5], 1u << (v & 31));
    d_flag[v] = 1;
}

// frontier marking from raw edge list (batch bitmap is L1/L2-resident)
__global__ void k_markE(const int* __restrict__ src, const int* __restrict__ dst) {
    for (int e = blockIdx.x * blockDim.x + threadIdx.x; e < NE;
         e += gridDim.x * blockDim.x) {
        int s = src[e], d = dst[e];
        if (getbit(d_bbit, d)) { d_flag[s] = 1; atomicOr(&d_fbit[s >> 5], 1u << (s & 31)); }
        if (getbit(d_bbit, s)) { d_flag[d] = 1; atomicOr(&d_fbit[d >> 5], 1u << (d & 31)); }
    }
}

__global__ void k_hist(const int* __restrict__ src, const int* __restrict__ dst) {
    for (int e = blockIdx.x * blockDim.x + threadIdx.x; e < NE;
         e += gridDim.x * blockDim.x) {
        atomicAdd(&d_cur_f[dst[e]], 1);
        atomicAdd(&d_cur_r[src[e]], 1);
    }
}

__device__ __forceinline__ int wscan(int x, int lane) {
#pragma unroll
    for (int o = 1; o < 32; o <<= 1) {
        int t = __shfl_up_sync(0xFFFFFFFFu, x, o);
        if (lane >= o) x += t;
    }
    return x;
}

__device__ __forceinline__ void scanA_body(const int* cnt, int* out, int which, int blk) {
    __shared__ int ws[32];
    int t = threadIdx.x, lane = t & 31, wid = t >> 5;
    int i = blk * 1024 + t;
    int v = (i < NN) ? cnt[i] : 0;
    int x = wscan(v, lane);
    if (lane == 31) ws[wid] = x;
    __syncthreads();
    if (wid == 0) ws[lane] = wscan(ws[lane], lane);
    __syncthreads();
    int off = wid ? ws[wid - 1] : 0;
    int incl = x + off;
    if (i < NN) out[i] = incl - v;
    if (t == 1023) d_bsum[which * 128 + blk] = incl;
}

__global__ void k_scanA01() {
    int which = blockIdx.x / NB_SCAN;
    int blk   = blockIdx.x % NB_SCAN;
    scanA_body(which ? d_cur_r : d_cur_f, which ? d_row_r : d_row_f, which, blk);
}
__global__ void k_scanA2() {
    scanA_body(d_flag, d_fpos, 2, blockIdx.x);
}

__device__ __forceinline__ void scanB_body(int which) {
    __shared__ int ws[4];
    int t = threadIdx.x, lane = t & 31, wid = t >> 5;
    int v = (t < NB_SCAN) ? d_bsum[which * 128 + t] : 0;
    int x = wscan(v, lane);
    if (lane == 31) ws[wid] = x;
    __syncthreads();
    int off = 0;
    for (int w2 = 0; w2 < wid; ++w2) off += ws[w2];
    d_bsum[which * 128 + t] = x + off - v;   // exclusive
}
__global__ void k_scanB01() { scanB_body(blockIdx.x); }     // grid=2
__global__ void k_scanB2()  { scanB_body(2); }              // grid=1

__global__ void k_scanC01() {
    int g = blockIdx.x * blockDim.x + threadIdx.x;
    int which = (g >= NN) ? 1 : 0;
    int i = g - which * NN;
    if (i >= NN) return;
    int* row = which ? d_row_r : d_row_f;
    int* cur = which ? d_cur_r : d_cur_f;
    int r = row[i] + d_bsum[which * 128 + (i >> 10)];
    row[i] = r;
    cur[i] = r;
    if (i == 0) row[NN] = NE;
}

// fill gated on frontier bitmap: only frontier-incident edge slots are
// written (~28%); non-frontier CSR ranges stay garbage and are never read.
__global__ void k_fill(const int* __restrict__ src, const int* __restrict__ dst,
                       const float* __restrict__ w) {
    for (int e = blockIdx.x * blockDim.x + threadIdx.x; e < NE;
         e += gridDim.x * blockDim.x) {
        int s = src[e], d = dst[e];
        int wb = __float_as_int(w[e]);
        if (getbit(d_fbit, d)) {
            int p = atomicAdd(&d_cur_f[d], 1);
            d_e_f[p] = make_int2(s, wb);
        }
        if (getbit(d_fbit, s)) {
            int q = atomicAdd(&d_cur_r[s], 1);
            d_e_r[q] = make_int2(d, wb);
        }
    }
}

__global__ void k_compact() {
    int i = blockIdx.x * blockDim.x + threadIdx.x;
    if (i >= NN) return;
    int pos = d_fpos[i] + d_bsum[2 * 128 + (i >> 10)];
    int f = d_flag[i];
    if (f) d_front[pos] = i;
    if (i == NN - 1) d_cnt = pos + f;
}

// ---------------- encoder: x = text @ W_enc + b_enc (tf32 mma.sync) --------
#define SA_S 136
#define SW_S 72
__global__ __launch_bounds__(128, 4)
void k_encMMA(const float* __restrict__ A, const float* __restrict__ W,
              const float* __restrict__ b) {
    extern __shared__ float sm[];
    float* sAh = sm;                        // [32][136]
    float* sAl = sm + 32 * SA_S;
    float* sWh = sm + 2 * 32 * SA_S;        // [32][72]
    float* sWl = sm + 2 * 32 * SA_S + 32 * SW_S;

    int tid  = threadIdx.x;
    int warp = tid >> 5, lane = tid & 31;
    int g = lane >> 2, tig = lane & 3;
    int row0 = blockIdx.x * 128;

    float acc[2][8][4];
#pragma unroll
    for (int mt = 0; mt < 2; ++mt)
#pragma unroll
        for (int nt = 0; nt < 8; ++nt)
#pragma unroll
            for (int q = 0; q < 4; ++q) acc[mt][nt][q] = 0.f;

    for (int kc = 0; kc < 12; ++kc) {
#pragma unroll
        for (int p = 0; p < 8; ++p) {
            int lin = tid + p * 128;
            int r = lin >> 3, kq = lin & 7;
            int gr = row0 + r; if (gr >= NN) gr = NN - 1;
            float4 v = *(const float4*)(A + (long long)gr * TXT + kc * 32 + kq * 4);
            float vv[4] = { v.x, v.y, v.z, v.w };
#pragma unroll
            for (int j = 0; j < 4; ++j) {
                int k = kq * 4 + j;
                int rw = r ^ (((k >> 2) & 3) << 3);
                float hi = tf32hi(vv[j]);
                sAh[k * SA_S + rw] = hi;
                sAl[k * SA_S + rw] = vv[j] - hi;
            }
        }
#pragma unroll
        for (int p = 0; p < 4; ++p) {
            int lin = tid + p * 128;
            int k = lin >> 4, nq = lin & 15;
            float4 v = *(const float4*)(W + (long long)(kc * 32 + k) * HID + nq * 4);
            float vv[4] = { v.x, v.y, v.z, v.w };
#pragma unroll
            for (int j = 0; j < 4; ++j) {
                float hi = tf32hi(vv[j]);
                sWh[k * SW_S + nq * 4 + j] = hi;
                sWl[k * SW_S + nq * 4 + j] = vv[j] - hi;
            }
        }
        __syncthreads();

#pragma unroll
        for (int ks = 0; ks < 4; ++ks) {
            int k0 = ks * 8 + tig;
            int k1 = k0 + 4;
            int x0 = ((k0 >> 2) & 3) << 3;
            int x1 = ((k1 >> 2) & 3) << 3;
            uint32_t ah[2][4], al[2][4];
#pragma unroll
            for (int mt = 0; mt < 2; ++mt) {
                int r = warp * 32 + mt * 16 + g;
                int rA0 = r ^ x0, rB0 = (r + 8) ^ x0;
                int rA1 = r ^ x1, rB1 = (r + 8) ^ x1;
                ah[mt][0] = __float_as_uint(sAh[k0 * SA_S + rA0]);
                ah[mt][1] = __float_as_uint(sAh[k0 * SA_S + rB0]);
                ah[mt][2] = __float_as_uint(sAh[k1 * SA_S + rA1]);
                ah[mt][3] = __float_as_uint(sAh[k1 * SA_S + rB1]);
                al[mt][0] = __float_as_uint(sAl[k0 * SA_S + rA0]);
                al[mt][1] = __float_as_uint(sAl[k0 * SA_S + rB0]);
                al[mt][2] = __float_as_uint(sAl[k1 * SA_S + rA1]);
                al[mt][3] = __float_as_uint(sAl[k1 * SA_S + rB1]);
            }
#pragma unroll
            for (int nt = 0; nt < 8; ++nt) {
                int cb = nt * 8 + g;
                uint32_t bh[2], bl[2];
                bh[0] = __float_as_uint(sWh[k0 * SW_S + cb]);
                bh[1] = __float_as_uint(sWh[k1 * SW_S + cb]);
                bl[0] = __float_as_uint(sWl[k0 * SW_S + cb]);
                bl[1] = __float_as_uint(sWl[k1 * SW_S + cb]);
#pragma unroll
                for (int mt = 0; mt < 2; ++mt) {
                    mma_tf32(acc[mt][nt], ah[mt], bh);
                    mma_tf32(acc[mt][nt], ah[mt], bl);
                    mma_tf32(acc[mt][nt], al[mt], bh);
                }
            }
        }
        __syncthreads();
    }

#pragma unroll
    for (int mt = 0; mt < 2; ++mt) {
#pragma unroll
        for (int nt = 0; nt < 8; ++nt) {
            int c = nt * 8 + 2 * tig;
            float2 bb = *(const float2*)(b + c);
            int r0 = row0 + warp * 32 + mt * 16 + g;
            if (r0 < NN) {
                float2 o = make_float2(acc[mt][nt][0] + bb.x,
                                       acc[mt][nt][1] + bb.y);
                *(float2*)(d_x + (long long)r0 * HID + c) = o;
            }
            int r1 = r0 + 8;
            if (r1 < NN) {
                float2 o = make_float2(acc[mt][nt][2] + bb.x,
                                       acc[mt][nt][3] + bb.y);
                *(float2*)(d_x + (long long)r1 * HID + c) = o;
            }
        }
    }
}

// ---------------- frontier aggregation, BOTH directions in one launch ------
__global__ void k_aggF2() {
    int M = d_cnt;
    int lane = threadIdx.x & 31;
    int w = blockIdx.x * (blockDim.x >> 5) + (threadIdx.x >> 5);
    int which = (w >= NN) ? 1 : 0;
    int idx = w - which * NN;
    if (idx >= M) return;
    int v = d_front[idx];
    const int*  row = which ? d_row_r : d_row_f;
    const int2* enb = which ? d_e_r   : d_e_f;
    float*      out = which ? d_nr    : d_nf;

    int beg = row[v], end = row[v + 1];
    float a0 = 0.f, a1 = 0.f;
#pragma unroll 4
    for (int e = beg; e < end; ++e) {
        int2 ed = enb[e];
        float wv = __int_as_float(ed.y);
        float2 xv = *(const float2*)(d_x + (long long)ed.x * HID + 2 * lane);
        a0 = fmaf(wv, xv.x, a0);
        a1 = fmaf(wv, xv.y, a1);
    }
    float inv = (end > beg) ? 1.0f / (float)(end - beg) : 0.f;
    ((float2*)(out + (long long)v * HID))[lane] = make_float2(a0 * inv, a1 * inv);
}

// ---------------- layer-0 update at frontier rows only ---------------------
__global__ __launch_bounds__(256, 2)
void k_updF(const float* __restrict__ Wsf, const float* __restrict__ Wnf,
            const float* __restrict__ bf,
            const float* __restrict__ Wsr, const float* __restrict__ Wnr,
            const float* __restrict__ br) {
    int M = d_cnt;
    int row0 = blockIdx.x * 128;
    if (row0 >= M) return;

    extern __shared__ float sm[];
    float (*sW)[64][64] = (float (*)[64][64])sm;        // 4 x 64 x 64 = 64KB
    float (*sX)[132] = (float (*)[132])(sm + 4 * 4096);
    float (*sF)[132] = (float (*)[132])(sm + 4 * 4096 + 16 * 132);
    float (*sR)[132] = (float (*)[132])(sm + 4 * 4096 + 32 * 132);

    int tid = threadIdx.x;
    int cb = tid & 15;
    int rb = tid >> 4;
    int c0 = cb * 4, r0 = rb * 8;

#pragma unroll
    for (int p = 0; p < 16; ++p) {
        int lin = (tid + p * 256) * 4;
        int m = lin >> 12, rem = lin & 4095;
        const float* srcw = (m == 0) ? Wsf : (m == 1) ? Wnf : (m == 2) ? Wsr : Wnr;
        *(float4*)&sW[m][rem >> 6][rem & 63] = *(const float4*)(srcw + rem);
    }

    unsigned long long accf[4][4], accr[4][4];
#pragma unroll
    for (int c = 0; c < 4; ++c) {
        float bvf = __ldg(bf + c0 + c), bvr = __ldg(br + c0 + c);
        unsigned long long pf = pack2(bvf, bvf), pr = pack2(bvr, bvr);
#pragma unroll
        for (int rp = 0; rp < 4; ++rp) { accf[rp][c] = pf; accr[rp][c] = pr; }
    }

    for (int kc = 0; kc < HID; kc += 16) {
        __syncthreads();
#pragma unroll
        for (int p = 0; p < 2; ++p) {
            int lin = tid + p * 256;
            int r = lin >> 2, c4 = (lin & 3) * 4;
            int gi = row0 + r;
            int node = d_front[(gi < M) ? gi : (M - 1)];
            long long base = (long long)node * HID + kc + c4;
            float4 vx = *(const float4*)(d_x + base);
            float4 vf = *(const float4*)(d_nf + base);
            float4 vr = *(const float4*)(d_nr + base);
            sX[c4 + 0][r] = vx.x; sX[c4 + 1][r] = vx.y; sX[c4 + 2][r] = vx.z; sX[c4 + 3][r] = vx.w;
            sF[c4 + 0][r] = vf.x; sF[c4 + 1][r] = vf.y; sF[c4 + 2][r] = vf.z; sF[c4 + 3][r] = vf.w;
            sR[c4 + 0][r] = vr.x; sR[c4 + 1][r] = vr.y; sR[c4 + 2][r] = vr.z; sR[c4 + 3][r] = vr.w;
        }
        __syncthreads();

#pragma unroll
        for (int k = 0; k < 16; ++k) {
            int gk = kc + k;
            ulonglong2 xA = *(const ulonglong2*)&sX[k][r0];
            ulonglong2 xB = *(const ulonglong2*)&sX[k][r0 + 4];
            ulonglong2 fA = *(const ulonglong2*)&sF[k][r0];
            ulonglong2 fB = *(const ulonglong2*)&sF[k][r0 + 4];
            ulonglong2 rA = *(const ulonglong2*)&sR[k][r0];
            ulonglong2 rB = *(const ulonglong2*)&sR[k][r0 + 4];
            unsigned long long x2[4] = { xA.x, xA.y, xB.x, xB.y };
            unsigned long long f2[4] = { fA.x, fA.y, fB.x, fB.y };
            unsigned long long r2[4] = { rA.x, rA.y, rB.x, rB.y };
            float4 wsf = *(const float4*)&sW[0][gk][c0];
            float4 wnf = *(const float4*)&sW[1][gk][c0];
            float4 wsr = *(const float4*)&sW[2][gk][c0];
            float4 wnr = *(const float4*)&sW[3][gk][c0];
            float vsf[4] = { wsf.x, wsf.y, wsf.z, wsf.w };
            float vnf[4] = { wnf.x, wnf.y, wnf.z, wnf.w };
            float vsr[4] = { wsr.x, wsr.y, wsr.z, wsr.w };
            float vnr[4] = { wnr.x, wnr.y, wnr.z, wnr.w };
#pragma unroll
            for (int c = 0; c < 4; ++c) {
                unsigned long long wsf2 = pack2(vsf[c], vsf[c]);
                unsigned long long wnf2 = pack2(vnf[c], vnf[c]);
                unsigned long long wsr2 = pack2(vsr[c], vsr[c]);
                unsigned long long wnr2 = pack2(vnr[c], vnr[c]);
#pragma unroll
                for (int rp = 0; rp < 4; ++rp) {
                    fma2(accf[rp][c], x2[rp], wsf2);
                    fma2(accf[rp][c], f2[rp], wnf2);
                    fma2(accr[rp][c], x2[rp], wsr2);
                    fma2(accr[rp][c], r2[rp], wnr2);
                }
            }
        }
    }

#pragma unroll
    for (int rp = 0; rp < 4; ++rp) {
#pragma unroll
        for (int h = 0; h < 2; ++h) {
            int gi = row0 + r0 + 2 * rp + h;
            if (gi >= M) continue;
            int node = d_front[gi];
            float* xp = d_x + (long long)node * HID + c0;
            float4 xv = *(const float4*)xp;
            float vf[4], vr[4];
#pragma unroll
            for (int c = 0; c < 4; ++c) {
                float lo, hi;
                unpack2(accf[rp][c], lo, hi); vf[c] = h ? hi : lo;
                unpack2(accr[rp][c], lo, hi); vr[c] = h ? hi : lo;
            }
            xv.x += fmaxf(vf[0], 0.f) + fmaxf(vr[0], 0.f);
            xv.y += fmaxf(vf[1], 0.f) + fmaxf(vr[1], 0.f);
            xv.z += fmaxf(vf[2], 0.f) + fmaxf(vr[2], 0.f);
            xv.w += fmaxf(vf[3], 0.f) + fmaxf(vr[3], 0.f);
            *(float4*)xp = xv;
        }
    }
}

// ---------------- layer 2 fused, batch nodes only + L2-normalize -----------
__global__ void k_batch(const int* __restrict__ ids,
                        const float* __restrict__ Wsf, const float* __restrict__ Wnf,
                        const float* __restrict__ bf,
                        const float* __restrict__ Wsr, const float* __restrict__ Wnr,
                        const float* __restrict__ br,
                        float* __restrict__ out) {
    extern __shared__ float sm[];
    float *sWsf = sm, *sWnf = sm + 4096, *sWsr = sm + 8192, *sWnr = sm + 12288;
    float *sbf  = sm + 16384, *sbr = sm + 16448;
    for (int i = threadIdx.x; i < 4096; i += blockDim.x) {
        sWsf[i] = Wsf[i]; sWnf[i] = Wnf[i]; sWsr[i] = Wsr[i]; sWnr[i] = Wnr[i];
    }
    if (threadIdx.x < 64) { sbf[threadIdx.x] = bf[threadIdx.x]; sbr[threadIdx.x] = br[threadIdx.x]; }
    __syncthreads();

    int lane = threadIdx.x & 31;
    int i = blockIdx.x * (blockDim.x >> 5) + (threadIdx.x >> 5);
    if (i >= NBATCH) return;
    int v = ids[i];

    float nf0 = 0.f, nf1 = 0.f;
    int beg = d_row_f[v], end = d_row_f[v + 1];
#pragma unroll 4
    for (int e = beg; e < end; ++e) {
        int2 ed = d_e_f[e];
        float wv = __int_as_float(ed.y);
        float2 xv = *(const float2*)(d_x + (long long)ed.x * HID + 2 * lane);
        nf0 = fmaf(wv, xv.x, nf0); nf1 = fmaf(wv, xv.y, nf1);
    }
    float inv = (end > beg) ? 1.0f / (float)(end - beg) : 0.f;
    nf0 *= inv; nf1 *= inv;

    float nr0 = 0.f, nr1 = 0.f;
    beg = d_row_r[v]; end = d_row_r[v + 1];
#pragma unroll 4
    for (int e = beg; e < end; ++e) {
        int2 ed = d_e_r[e];
        float wv = __int_as_float(ed.y);
        float2 xv = *(const float2*)(d_x + (long long)ed.x * HID + 2 * lane);
        nr0 = fmaf(wv, xv.x, nr0); nr1 = fmaf(wv, xv.y, nr1);
    }
    inv = (end > beg) ? 1.0f / (float)(end - beg) : 0.f;
    nr0 *= inv; nr1 *= inv;

    float2 xv = *(const float2*)(d_x + (long long)v * HID + 2 * lane);
    float af0 = sbf[2 * lane], af1 = sbf[2 * lane + 1];
    float ar0 = sbr[2 * lane], ar1 = sbr[2 * lane + 1];

#pragma unroll 4
    for (int k2 = 0; k2 < 32; ++k2) {
        float xa = __shfl_sync(0xFFFFFFFFu, xv.x, k2);
        float xb = __shfl_sync(0xFFFFFFFFu, xv.y, k2);
        float fa = __shfl_sync(0xFFFFFFFFu, nf0, k2);
        float fb = __shfl_sync(0xFFFFFFFFu, nf1, k2);
        float ra = __shfl_sync(0xFFFFFFFFu, nr0, k2);
        float rb = __shfl_sync(0xFFFFFFFFu, nr1, k2);
        int ka = 2 * k2, kb = 2 * k2 + 1;
        float2 w;
        w = *(const float2*)(sWsf + ka * 64 + 2 * lane); af0 = fmaf(xa, w.x, af0); af1 = fmaf(xa, w.y, af1);
        w = *(const float2*)(sWsf + kb * 64 + 2 * lane); af0 = fmaf(xb, w.x, af0); af1 = fmaf(xb, w.y, af1);
        w = *(const float2*)(sWnf + ka * 64 + 2 * lane); af0 = fmaf(fa, w.x, af0); af1 = fmaf(fa, w.y, af1);
        w = *(const float2*)(sWnf + kb * 64 + 2 * lane); af0 = fmaf(fb, w.x, af0); af1 = fmaf(fb, w.y, af1);
        w = *(const float2*)(sWsr + ka * 64 + 2 * lane); ar0 = fmaf(xa, w.x, ar0); ar1 = fmaf(xa, w.y, ar1);
        w = *(const float2*)(sWsr + kb * 64 + 2 * lane); ar0 = fmaf(xb, w.x, ar0); ar1 = fmaf(xb, w.y, ar1);
        w = *(const float2*)(sWnr + ka * 64 + 2 * lane); ar0 = fmaf(ra, w.x, ar0); ar1 = fmaf(ra, w.y, ar1);
        w = *(const float2*)(sWnr + kb * 64 + 2 * lane); ar0 = fmaf(rb, w.x, ar0); ar1 = fmaf(rb, w.y, ar1);
    }
    float u0 = xv.x + fmaxf(af0, 0.f) + fmaxf(ar0, 0.f);
    float u1 = xv.y + fmaxf(af1, 0.f) + fmaxf(ar1, 0.f);
    float ss = u0 * u0 + u1 * u1;
#pragma unroll
    for (int o = 16; o > 0; o >>= 1) ss += __shfl_xor_sync(0xFFFFFFFFu, ss, o);
    float rinv = 1.0f / sqrtf(ss);
    ((float2*)(out + (long long)i * HID))[lane] = make_float2(u0 * rinv, u1 * rinv);
}

// ---------------- launch ----------------------------------------------------
extern "C" void kernel_launch(void* const* d_in, const int* in_sizes, int n_in,
                              void* d_out, int out_size) {
    const float* text = (const float*)d_in[0];
    const float* w    = (const float*)d_in[1];
    const float* Wenc = (const float*)d_in[2];
    const float* benc = (const float*)d_in[3];
    const float* Wsf  = (const float*)d_in[4];
    const float* Wnf  = (const float*)d_in[5];
    const float* bf   = (const float*)d_in[6];
    const float* Wsr  = (const float*)d_in[7];
    const float* Wnr  = (const float*)d_in[8];
    const float* br   = (const float*)d_in[9];
    const int*   src  = (const int*)d_in[10];
    const int*   dst  = (const int*)d_in[11];
    const int*   ids  = (const int*)d_in[12];
    float* out = (float*)d_out;

    const int UPD_SMEM   = (4 * 4096 + 48 * 132) * (int)sizeof(float);  // 90,880
    const int BATCH_SMEM = (4 * 4096 + 128) * (int)sizeof(float);       // 66,048
    const int ENC_SMEM   = (2 * 32 * SA_S + 2 * 32 * SW_S) * (int)sizeof(float); // 53,248

    static cudaStream_t s2 = 0, s3 = 0;
    static cudaEvent_t evFork = 0, evJoinEnc = 0, evZero = 0, evMark = 0, evFront = 0;
    if (s2 == 0) {
        cudaStreamCreateWithFlags(&s2, cudaStreamNonBlocking);
        cudaStreamCreateWithFlags(&s3, cudaStreamNonBlocking);
        cudaEventCreateWithFlags(&evFork,    cudaEventDisableTiming);
        cudaEventCreateWithFlags(&evJoinEnc, cudaEventDisableTiming);
        cudaEventCreateWithFlags(&evZero,    cudaEventDisableTiming);
        cudaEventCreateWithFlags(&evMark,    cudaEventDisableTiming);
        cudaEventCreateWithFlags(&evFront,   cudaEventDisableTiming);
        cudaFuncSetAttribute(k_updF,   cudaFuncAttributeMaxDynamicSharedMemorySize, UPD_SMEM);
        cudaFuncSetAttribute(k_batch,  cudaFuncAttributeMaxDynamicSharedMemorySize, BATCH_SMEM);
        cudaFuncSetAttribute(k_encMMA, cudaFuncAttributeMaxDynamicSharedMemorySize, ENC_SMEM);
    }

    // branch 1: encoder (independent of everything)
    cudaEventRecord(evFork, 0);
    cudaStreamWaitEvent(s2, evFork, 0);
    k_encMMA<<<(NN + 127) / 128, 128, ENC_SMEM, s2>>>(text, Wenc, benc);
    cudaEventRecord(evJoinEnc, s2);

    // main: zero, then CSR hist/scans
    k_zero<<<(NN + 255) / 256, 256>>>();
    cudaEventRecord(evZero, 0);

    // branch 2: frontier from raw edge list (needs only zeroed flags/bitmaps)
    cudaStreamWaitEvent(s3, evZero, 0);
    k_bset<<<1, NBATCH, 0, s3>>>(ids);
    k_markE<<<1024, 256, 0, s3>>>(src, dst);
    cudaEventRecord(evMark, s3);
    k_scanA2<<<NB_SCAN, 1024, 0, s3>>>();
    k_scanB2<<<1, 128, 0, s3>>>();
    k_compact<<<(NN + 255) / 256, 256, 0, s3>>>();
    cudaEventRecord(evFront, s3);

    // main CSR chain (hist ungated; fill gated on frontier bitmap)
    k_hist<<<1024, 256>>>(src, dst);
    k_scanA01<<<2 * NB_SCAN, 1024>>>();
    k_scanB01<<<2, 128>>>();
    k_scanC01<<<(2 * NN + 255) / 256, 256>>>();
    cudaStreamWaitEvent(0, evMark, 0);       // fill needs d_fbit
    k_fill<<<1024, 256>>>(src, dst, w);

    // join all branches before layer-0
    cudaStreamWaitEvent(0, evJoinEnc, 0);
    cudaStreamWaitEvent(0, evFront, 0);

    // layer 0 restricted to frontier: both directions in ONE launch
    k_aggF2<<<2 * ((NN + 7) / 8), 256>>>();
    k_updF<<<(NN + 127) / 128, 256, UPD_SMEM>>>(Wsf, Wnf, bf, Wsr, Wnr, br);

    // layer 1: only at the 1024 output nodes (fused agg+update+norm)
    k_batch<<<NBATCH / 8, 256, BATCH_SMEM>>>(ids,
        Wsf + 4096, Wnf + 4096, bf + 64,
        Wsr + 4096, Wnr + 4096, br + 64, out);
}

// round 12
// speedup vs baseline: 1.2750x; 1.0097x over previous
#include <cuda_runtime.h>
#include <cstdint>

#define NN   100000
#define NE   1600000
#define HID  64
#define TXT  384
#define NBATCH 1024
#define NB_SCAN 98            // ceil(NN/1024)
#define NBW  3125             // ceil(NN/32) bitmap words
#define ENC_SPLIT 50048       // 391 blocks of 128 rows for the MMA encoder

// ---------------- scratch (device globals; no allocation allowed) ----------
__device__ int      d_row_f[NN + 1];
__device__ int      d_row_r[NN + 1];
__device__ int      d_cur_f[NN];
__device__ int      d_cur_r[NN];
__device__ int      d_flag[NN];
__device__ int      d_fpos[NN];
__device__ int      d_front[NN];
__device__ int      d_cnt;
__device__ unsigned d_bbit[NBW];      // batch bitmap
__device__ unsigned d_fbit[NBW];      // frontier bitmap
__device__ int2     d_e_f[NE];        // (neighbor, weight-bits) fused
__device__ int2     d_e_r[NE];
__device__ float    d_x [NN * HID];
__device__ float    d_nf[NN * HID];
__device__ float    d_nr[NN * HID];
__device__ int      d_bsum[384];

// ---------------- f32x2 helpers ---------------------------------------------
__device__ __forceinline__ unsigned long long pack2(float lo, float hi) {
    unsigned long long r;
    asm("mov.b64 %0, {%1, %2};" : "=l"(r) : "f"(lo), "f"(hi));
    return r;
}
__device__ __forceinline__ void unpack2(unsigned long long v, float& lo, float& hi) {
    asm("mov.b64 {%0, %1}, %2;" : "=f"(lo), "=f"(hi) : "l"(v));
}
__device__ __forceinline__ void fma2(unsigned long long& d,
                                     unsigned long long a, unsigned long long b) {
    asm("fma.rn.f32x2 %0, %1, %2, %0;" : "+l"(d) : "l"(a), "l"(b));
}
__device__ __forceinline__ bool getbit(const unsigned* bm, int v) {
    return (bm[v >> 5] >> (v & 31)) & 1u;
}

// ---------------- tf32 mma helpers ------------------------------------------
__device__ __forceinline__ float tf32hi(float v) {
    return __int_as_float(__float_as_int(v) & 0xFFFFE000);
}
__device__ __forceinline__ void mma_tf32(float* d, const uint32_t* a,
                                         const uint32_t* b) {
    asm volatile(
        "mma.sync.aligned.m16n8k8.row.col.f32.tf32.tf32.f32 "
        "{%0,%1,%2,%3}, {%4,%5,%6,%7}, {%8,%9}, {%0,%1,%2,%3};"
        : "+f"(d[0]), "+f"(d[1]), "+f"(d[2]), "+f"(d[3])
        : "r"(a[0]), "r"(a[1]), "r"(a[2]), "r"(a[3]), "r"(b[0]), "r"(b[1]));
}

// ---------------- CSR construction -----------------------------------------
__global__ void k_zero() {
    int i = blockIdx.x * blockDim.x + threadIdx.x;
    if (i < NN) { d_cur_f[i] = 0; d_cur_r[i] = 0; d_flag[i] = 0; }
    if (i < NBW) { d_bbit[i] = 0; d_fbit[i] = 0; }
}

__global__ void k_bset(const int* __restrict__ ids) {
    int v = ids[threadIdx.x];
    atomicOr(&d_bbit[v >> 5], 1u << (v & 31));
    atomicOr(&d_fbit[v >> 5], 1u << (v & 31));
    d_flag[v] = 1;
}

__global__ void k_markE(const int* __restrict__ src, const int* __restrict__ dst) {
    for (int e = blockIdx.x * blockDim.x + threadIdx.x; e < NE;
         e += gridDim.x * blockDim.x) {
        int s = src[e], d = dst[e];
        if (getbit(d_bbit, d)) { d_flag[s] = 1; atomicOr(&d_fbit[s >> 5], 1u << (s & 31)); }
        if (getbit(d_bbit, s)) { d_flag[d] = 1; atomicOr(&d_fbit[d >> 5], 1u << (d & 31)); }
    }
}

__global__ void k_hist(const int* __restrict__ src, const int* __restrict__ dst) {
    for (int e = blockIdx.x * blockDim.x + threadIdx.x; e < NE;
         e += gridDim.x * blockDim.x) {
        atomicAdd(&d_cur_f[dst[e]], 1);
        atomicAdd(&d_cur_r[src[e]], 1);
    }
}

__device__ __forceinline__ int wscan(int x, int lane) {
#pragma unroll
    for (int o = 1; o < 32; o <<= 1) {
        int t = __shfl_up_sync(0xFFFFFFFFu, x, o);
        if (lane >= o) x += t;
    }
    return x;
}

__device__ __forceinline__ void scanA_body(const int* cnt, int* out, int which, int blk) {
    __shared__ int ws[32];
    int t = threadIdx.x, lane = t & 31, wid = t >> 5;
    int i = blk * 1024 + t;
    int v = (i < NN) ? cnt[i] : 0;
    int x = wscan(v, lane);
    if (lane == 31) ws[wid] = x;
    __syncthreads();
    if (wid == 0) ws[lane] = wscan(ws[lane], lane);
    __syncthreads();
    int off = wid ? ws[wid - 1] : 0;
    int incl = x + off;
    if (i < NN) out[i] = incl - v;
    if (t == 1023) d_bsum[which * 128 + blk] = incl;
}

__global__ void k_scanA01() {
    int which = blockIdx.x / NB_SCAN;
    int blk   = blockIdx.x % NB_SCAN;
    scanA_body(which ? d_cur_r : d_cur_f, which ? d_row_r : d_row_f, which, blk);
}
__global__ void k_scanA2() {
    scanA_body(d_flag, d_fpos, 2, blockIdx.x);
}

__device__ __forceinline__ void scanB_body(int which) {
    __shared__ int ws[4];
    int t = threadIdx.x, lane = t & 31, wid = t >> 5;
    int v = (t < NB_SCAN) ? d_bsum[which * 128 + t] : 0;
    int x = wscan(v, lane);
    if (lane == 31) ws[wid] = x;
    __syncthreads();
    int off = 0;
    for (int w2 = 0; w2 < wid; ++w2) off += ws[w2];
    d_bsum[which * 128 + t] = x + off - v;   // exclusive
}
__global__ void k_scanB01() { scanB_body(blockIdx.x); }     // grid=2
__global__ void k_scanB2()  { scanB_body(2); }              // grid=1

__global__ void k_scanC01() {
    int g = blockIdx.x * blockDim.x + threadIdx.x;
    int which = (g >= NN) ? 1 : 0;
    int i = g - which * NN;
    if (i >= NN) return;
    int* row = which ? d_row_r : d_row_f;
    int* cur = which ? d_cur_r : d_cur_f;
    int r = row[i] + d_bsum[which * 128 + (i >> 10)];
    row[i] = r;
    cur[i] = r;
    if (i == 0) row[NN] = NE;
}

// fill gated on frontier bitmap
__global__ void k_fill(const int* __restrict__ src, const int* __restrict__ dst,
                       const float* __restrict__ w) {
    for (int e = blockIdx.x * blockDim.x + threadIdx.x; e < NE;
         e += gridDim.x * blockDim.x) {
        int s = src[e], d = dst[e];
        int wb = __float_as_int(w[e]);
        if (getbit(d_fbit, d)) {
            int p = atomicAdd(&d_cur_f[d], 1);
            d_e_f[p] = make_int2(s, wb);
        }
        if (getbit(d_fbit, s)) {
            int q = atomicAdd(&d_cur_r[s], 1);
            d_e_r[q] = make_int2(d, wb);
        }
    }
}

__global__ void k_compact() {
    int i = blockIdx.x * blockDim.x + threadIdx.x;
    if (i >= NN) return;
    int pos = d_fpos[i] + d_bsum[2 * 128 + (i >> 10)];
    int f = d_flag[i];
    if (f) d_front[pos] = i;
    if (i == NN - 1) d_cnt = pos + f;
}

// ---------------- encoder A: FMA2 SGEMM (rows [rowBase, rowEnd)) -----------
__global__ __launch_bounds__(128, 4)
void k_enc2(const float* __restrict__ A, const float* __restrict__ W,
            const float* __restrict__ b, int rowBase, int rowEnd) {
    __shared__ float sA[32][132];     // [k][row], padded
    __shared__ float sW[32][64];      // [k][col]

    int tid = threadIdx.x;
    int row0 = rowBase + blockIdx.x * 128;
    int cb = tid & 7;
    int rb = tid >> 3;
    int c0 = cb * 8, r0 = rb * 8;

    unsigned long long acc[4][8];
#pragma unroll
    for (int c = 0; c < 8; ++c) {
        float bv = __ldg(b + c0 + c);
        unsigned long long bp = pack2(bv, bv);
#pragma unroll
        for (int rp = 0; rp < 4; ++rp) acc[rp][c] = bp;
    }

    for (int kc = 0; kc < TXT; kc += 32) {
#pragma unroll
        for (int p = 0; p < 8; ++p) {
            int lin = tid + p * 128;
            int r = lin >> 3, c4 = (lin & 7) * 4;
            int gr = row0 + r; if (gr >= rowEnd) gr = rowEnd - 1;
            float4 v = *(const float4*)(A + (long long)gr * TXT + kc + c4);
            sA[c4 + 0][r] = v.x; sA[c4 + 1][r] = v.y;
            sA[c4 + 2][r] = v.z; sA[c4 + 3][r] = v.w;
        }
#pragma unroll
        for (int p = 0; p < 4; ++p) {
            int lin = tid + p * 128;
            int k = lin >> 4, cc = (lin & 15) * 4;
            *(float4*)&sW[k][cc] = *(const float4*)(W + (kc + k) * 64 + cc);
        }
        __syncthreads();

#pragma unroll
        for (int k = 0; k < 32; ++k) {
            ulonglong2 aA = *(const ulonglong2*)&sA[k][r0];
            ulonglong2 aB = *(const ulonglong2*)&sA[k][r0 + 4];
            unsigned long long a2[4] = { aA.x, aA.y, aB.x, aB.y };
            float4 w0 = *(const float4*)&sW[k][c0];
            float4 w1 = *(const float4*)&sW[k][c0 + 4];
            float wv[8] = { w0.x, w0.y, w0.z, w0.w, w1.x, w1.y, w1.z, w1.w };
#pragma unroll
            for (int c = 0; c < 8; ++c) {
                unsigned long long w2 = pack2(wv[c], wv[c]);
#pragma unroll
                for (int rp = 0; rp < 4; ++rp) fma2(acc[rp][c], a2[rp], w2);
            }
        }
        __syncthreads();
    }

#pragma unroll
    for (int rp = 0; rp < 4; ++rp) {
#pragma unroll
        for (int h = 0; h < 2; ++h) {
            int gr = row0 + r0 + 2 * rp + h;
            if (gr >= rowEnd) continue;
            float v[8];
#pragma unroll
            for (int c = 0; c < 8; ++c) {
                float lo, hi; unpack2(acc[rp][c], lo, hi);
                v[c] = h ? hi : lo;
            }
            float* op = d_x + (long long)gr * HID + c0;
            *(float4*)op       = make_float4(v[0], v[1], v[2], v[3]);
            *(float4*)(op + 4) = make_float4(v[4], v[5], v[6], v[7]);
        }
    }
}

// ---------------- encoder B: tf32 mma.sync (rows [rowBase, rowEnd)) --------
#define SA_S 136
#define SW_S 72
__global__ __launch_bounds__(128, 4)
void k_encMMA(const float* __restrict__ A, const float* __restrict__ W,
              const float* __restrict__ b, int rowBase, int rowEnd) {
    extern __shared__ float sm[];
    float* sAh = sm;                        // [32][136]
    float* sAl = sm + 32 * SA_S;
    float* sWh = sm + 2 * 32 * SA_S;        // [32][72]
    float* sWl = sm + 2 * 32 * SA_S + 32 * SW_S;

    int tid  = threadIdx.x;
    int warp = tid >> 5, lane = tid & 31;
    int g = lane >> 2, tig = lane & 3;
    int row0 = rowBase + blockIdx.x * 128;

    float acc[2][8][4];
#pragma unroll
    for (int mt = 0; mt < 2; ++mt)
#pragma unroll
        for (int nt = 0; nt < 8; ++nt)
#pragma unroll
            for (int q = 0; q < 4; ++q) acc[mt][nt][q] = 0.f;

    for (int kc = 0; kc < 12; ++kc) {
#pragma unroll
        for (int p = 0; p < 8; ++p) {
            int lin = tid + p * 128;
            int r = lin >> 3, kq = lin & 7;
            int gr = row0 + r; if (gr >= rowEnd) gr = rowEnd - 1;
            float4 v = *(const float4*)(A + (long long)gr * TXT + kc * 32 + kq * 4);
            float vv[4] = { v.x, v.y, v.z, v.w };
#pragma unroll
            for (int j = 0; j < 4; ++j) {
                int k = kq * 4 + j;
                int rw = r ^ (((k >> 2) & 3) << 3);
                float hi = tf32hi(vv[j]);
                sAh[k * SA_S + rw] = hi;
                sAl[k * SA_S + rw] = vv[j] - hi;
            }
        }
#pragma unroll
        for (int p = 0; p < 4; ++p) {
            int lin = tid + p * 128;
            int k = lin >> 4, nq = lin & 15;
            float4 v = *(const float4*)(W + (long long)(kc * 32 + k) * HID + nq * 4);
            float vv[4] = { v.x, v.y, v.z, v.w };
#pragma unroll
            for (int j = 0; j < 4; ++j) {
                float hi = tf32hi(vv[j]);
                sWh[k * SW_S + nq * 4 + j] = hi;
                sWl[k * SW_S + nq * 4 + j] = vv[j] - hi;
            }
        }
        __syncthreads();

#pragma unroll
        for (int ks = 0; ks < 4; ++ks) {
            int k0 = ks * 8 + tig;
            int k1 = k0 + 4;
            int x0 = ((k0 >> 2) & 3) << 3;
            int x1 = ((k1 >> 2) & 3) << 3;
            uint32_t ah[2][4], al[2][4];
#pragma unroll
            for (int mt = 0; mt < 2; ++mt) {
                int r = warp * 32 + mt * 16 + g;
                int rA0 = r ^ x0, rB0 = (r + 8) ^ x0;
                int rA1 = r ^ x1, rB1 = (r + 8) ^ x1;
                ah[mt][0] = __float_as_uint(sAh[k0 * SA_S + rA0]);
                ah[mt][1] = __float_as_uint(sAh[k0 * SA_S + rB0]);
                ah[mt][2] = __float_as_uint(sAh[k1 * SA_S + rA1]);
                ah[mt][3] = __float_as_uint(sAh[k1 * SA_S + rB1]);
                al[mt][0] = __float_as_uint(sAl[k0 * SA_S + rA0]);
                al[mt][1] = __float_as_uint(sAl[k0 * SA_S + rB0]);
                al[mt][2] = __float_as_uint(sAl[k1 * SA_S + rA1]);
                al[mt][3] = __float_as_uint(sAl[k1 * SA_S + rB1]);
            }
#pragma unroll
            for (int nt = 0; nt < 8; ++nt) {
                int cb = nt * 8 + g;
                uint32_t bh[2], bl[2];
                bh[0] = __float_as_uint(sWh[k0 * SW_S + cb]);
                bh[1] = __float_as_uint(sWh[k1 * SW_S + cb]);
                bl[0] = __float_as_uint(sWl[k0 * SW_S + cb]);
                bl[1] = __float_as_uint(sWl[k1 * SW_S + cb]);
#pragma unroll
                for (int mt = 0; mt < 2; ++mt) {
                    mma_tf32(acc[mt][nt], ah[mt], bh);
                    mma_tf32(acc[mt][nt], ah[mt], bl);
                    mma_tf32(acc[mt][nt], al[mt], bh);
                }
            }
        }
        __syncthreads();
    }

#pragma unroll
    for (int mt = 0; mt < 2; ++mt) {
#pragma unroll
        for (int nt = 0; nt < 8; ++nt) {
            int c = nt * 8 + 2 * tig;
            float2 bb = *(const float2*)(b + c);
            int r0 = row0 + warp * 32 + mt * 16 + g;
            if (r0 < rowEnd) {
                float2 o = make_float2(acc[mt][nt][0] + bb.x,
                                       acc[mt][nt][1] + bb.y);
                *(float2*)(d_x + (long long)r0 * HID + c) = o;
            }
            int r1 = r0 + 8;
            if (r1 < rowEnd) {
                float2 o = make_float2(acc[mt][nt][2] + bb.x,
                                       acc[mt][nt][3] + bb.y);
                *(float2*)(d_x + (long long)r1 * HID + c) = o;
            }
        }
    }
}

// ---------------- frontier aggregation, BOTH directions in one launch ------
__global__ void k_aggF2() {
    int M = d_cnt;
    int lane = threadIdx.x & 31;
    int w = blockIdx.x * (blockDim.x >> 5) + (threadIdx.x >> 5);
    int which = (w >= NN) ? 1 : 0;
    int idx = w - which * NN;
    if (idx >= M) return;
    int v = d_front[idx];
    const int*  row = which ? d_row_r : d_row_f;
    const int2* enb = which ? d_e_r   : d_e_f;
    float*      out = which ? d_nr    : d_nf;

    int beg = row[v], end = row[v + 1];
    float a0 = 0.f, a1 = 0.f;
#pragma unroll 4
    for (int e = beg; e < end; ++e) {
        int2 ed = enb[e];
        float wv = __int_as_float(ed.y);
        float2 xv = *(const float2*)(d_x + (long long)ed.x * HID + 2 * lane);
        a0 = fmaf(wv, xv.x, a0);
        a1 = fmaf(wv, xv.y, a1);
    }
    float inv = (end > beg) ? 1.0f / (float)(end - beg) : 0.f;
    ((float2*)(out + (long long)v * HID))[lane] = make_float2(a0 * inv, a1 * inv);
}

// ---------------- layer-0 update at frontier rows only ---------------------
__global__ __launch_bounds__(256, 2)
void k_updF(const float* __restrict__ Wsf, const float* __restrict__ Wnf,
            const float* __restrict__ bf,
            const float* __restrict__ Wsr, const float* __restrict__ Wnr,
            const float* __restrict__ br) {
    int M = d_cnt;
    int row0 = blockIdx.x * 128;
    if (row0 >= M) return;

    extern __shared__ float sm[];
    float (*sW)[64][64] = (float (*)[64][64])sm;        // 4 x 64 x 64 = 64KB
    float (*sX)[132] = (float (*)[132])(sm + 4 * 4096);
    float (*sF)[132] = (float (*)[132])(sm + 4 * 4096 + 16 * 132);
    float (*sR)[132] = (float (*)[132])(sm + 4 * 4096 + 32 * 132);

    int tid = threadIdx.x;
    int cb = tid & 15;
    int rb = tid >> 4;
    int c0 = cb * 4, r0 = rb * 8;

#pragma unroll
    for (int p = 0; p < 16; ++p) {
        int lin = (tid + p * 256) * 4;
        int m = lin >> 12, rem = lin & 4095;
        const float* srcw = (m == 0) ? Wsf : (m == 1) ? Wnf : (m == 2) ? Wsr : Wnr;
        *(float4*)&sW[m][rem >> 6][rem & 63] = *(const float4*)(srcw + rem);
    }

    unsigned long long accf[4][4], accr[4][4];
#pragma unroll
    for (int c = 0; c < 4; ++c) {
        float bvf = __ldg(bf + c0 + c), bvr = __ldg(br + c0 + c);
        unsigned long long pf = pack2(bvf, bvf), pr = pack2(bvr, bvr);
#pragma unroll
        for (int rp = 0; rp < 4; ++rp) { accf[rp][c] = pf; accr[rp][c] = pr; }
    }

    for (int kc = 0; kc < HID; kc += 16) {
        __syncthreads();
#pragma unroll
        for (int p = 0; p < 2; ++p) {
            int lin = tid + p * 256;
            int r = lin >> 2, c4 = (lin & 3) * 4;
            int gi = row0 + r;
            int node = d_front[(gi < M) ? gi : (M - 1)];
            long long base = (long long)node * HID + kc + c4;
            float4 vx = *(const float4*)(d_x + base);
            float4 vf = *(const float4*)(d_nf + base);
            float4 vr = *(const float4*)(d_nr + base);
            sX[c4 + 0][r] = vx.x; sX[c4 + 1][r] = vx.y; sX[c4 + 2][r] = vx.z; sX[c4 + 3][r] = vx.w;
            sF[c4 + 0][r] = vf.x; sF[c4 + 1][r] = vf.y; sF[c4 + 2][r] = vf.z; sF[c4 + 3][r] = vf.w;
            sR[c4 + 0][r] = vr.x; sR[c4 + 1][r] = vr.y; sR[c4 + 2][r] = vr.z; sR[c4 + 3][r] = vr.w;
        }
        __syncthreads();

#pragma unroll
        for (int k = 0; k < 16; ++k) {
            int gk = kc + k;
            ulonglong2 xA = *(const ulonglong2*)&sX[k][r0];
            ulonglong2 xB = *(const ulonglong2*)&sX[k][r0 + 4];
            ulonglong2 fA = *(const ulonglong2*)&sF[k][r0];
            ulonglong2 fB = *(const ulonglong2*)&sF[k][r0 + 4];
            ulonglong2 rA = *(const ulonglong2*)&sR[k][r0];
            ulonglong2 rB = *(const ulonglong2*)&sR[k][r0 + 4];
            unsigned long long x2[4] = { xA.x, xA.y, xB.x, xB.y };
            unsigned long long f2[4] = { fA.x, fA.y, fB.x, fB.y };
            unsigned long long r2[4] = { rA.x, rA.y, rB.x, rB.y };
            float4 wsf = *(const float4*)&sW[0][gk][c0];
            float4 wnf = *(const float4*)&sW[1][gk][c0];
            float4 wsr = *(const float4*)&sW[2][gk][c0];
            float4 wnr = *(const float4*)&sW[3][gk][c0];
            float vsf[4] = { wsf.x, wsf.y, wsf.z, wsf.w };
            float vnf[4] = { wnf.x, wnf.y, wnf.z, wnf.w };
            float vsr[4] = { wsr.x, wsr.y, wsr.z, wsr.w };
            float vnr[4] = { wnr.x, wnr.y, wnr.z, wnr.w };
#pragma unroll
            for (int c = 0; c < 4; ++c) {
                unsigned long long wsf2 = pack2(vsf[c], vsf[c]);
                unsigned long long wnf2 = pack2(vnf[c], vnf[c]);
                unsigned long long wsr2 = pack2(vsr[c], vsr[c]);
                unsigned long long wnr2 = pack2(vnr[c], vnr[c]);
#pragma unroll
                for (int rp = 0; rp < 4; ++rp) {
                    fma2(accf[rp][c], x2[rp], wsf2);
                    fma2(accf[rp][c], f2[rp], wnf2);
                    fma2(accr[rp][c], x2[rp], wsr2);
                    fma2(accr[rp][c], r2[rp], wnr2);
                }
            }
        }
    }

#pragma unroll
    for (int rp = 0; rp < 4; ++rp) {
#pragma unroll
        for (int h = 0; h < 2; ++h) {
            int gi = row0 + r0 + 2 * rp + h;
            if (gi >= M) continue;
            int node = d_front[gi];
            float* xp = d_x + (long long)node * HID + c0;
            float4 xv = *(const float4*)xp;
            float vf[4], vr[4];
#pragma unroll
            for (int c = 0; c < 4; ++c) {
                float lo, hi;
                unpack2(accf[rp][c], lo, hi); vf[c] = h ? hi : lo;
                unpack2(accr[rp][c], lo, hi); vr[c] = h ? hi : lo;
            }
            xv.x += fmaxf(vf[0], 0.f) + fmaxf(vr[0], 0.f);
            xv.y += fmaxf(vf[1], 0.f) + fmaxf(vr[1], 0.f);
            xv.z += fmaxf(vf[2], 0.f) + fmaxf(vr[2], 0.f);
            xv.w += fmaxf(vf[3], 0.f) + fmaxf(vr[3], 0.f);
            *(float4*)xp = xv;
        }
    }
}

// ---------------- layer 2 fused, batch nodes only + L2-normalize -----------
__global__ void k_batch(const int* __restrict__ ids,
                        const float* __restrict__ Wsf, const float* __restrict__ Wnf,
                        const float* __restrict__ bf,
                        const float* __restrict__ Wsr, const float* __restrict__ Wnr,
                        const float* __restrict__ br,
                        float* __restrict__ out) {
    extern __shared__ float sm[];
    float *sWsf = sm, *sWnf = sm + 4096, *sWsr = sm + 8192, *sWnr = sm + 12288;
    float *sbf  = sm + 16384, *sbr = sm + 16448;
    for (int i = threadIdx.x; i < 4096; i += blockDim.x) {
        sWsf[i] = Wsf[i]; sWnf[i] = Wnf[i]; sWsr[i] = Wsr[i]; sWnr[i] = Wnr[i];
    }
    if (threadIdx.x < 64) { sbf[threadIdx.x] = bf[threadIdx.x]; sbr[threadIdx.x] = br[threadIdx.x]; }
    __syncthreads();

    int lane = threadIdx.x & 31;
    int i = blockIdx.x * (blockDim.x >> 5) + (threadIdx.x >> 5);
    if (i >= NBATCH) return;
    int v = ids[i];

    float nf0 = 0.f, nf1 = 0.f;
    int beg = d_row_f[v], end = d_row_f[v + 1];
#pragma unroll 4
    for (int e = beg; e < end; ++e) {
        int2 ed = d_e_f[e];
        float wv = __int_as_float(ed.y);
        float2 xv = *(const float2*)(d_x + (long long)ed.x * HID + 2 * lane);
        nf0 = fmaf(wv, xv.x, nf0); nf1 = fmaf(wv, xv.y, nf1);
    }
    float inv = (end > beg) ? 1.0f / (float)(end - beg) : 0.f;
    nf0 *= inv; nf1 *= inv;

    float nr0 = 0.f, nr1 = 0.f;
    beg = d_row_r[v]; end = d_row_r[v + 1];
#pragma unroll 4
    for (int e = beg; e < end; ++e) {
        int2 ed = d_e_r[e];
        float wv = __int_as_float(ed.y);
        float2 xv = *(const float2*)(d_x + (long long)ed.x * HID + 2 * lane);
        nr0 = fmaf(wv, xv.x, nr0); nr1 = fmaf(wv, xv.y, nr1);
    }
    inv = (end > beg) ? 1.0f / (float)(end - beg) : 0.f;
    nr0 *= inv; nr1 *= inv;

    float2 xv = *(const float2*)(d_x + (long long)v * HID + 2 * lane);
    float af0 = sbf[2 * lane], af1 = sbf[2 * lane + 1];
    float ar0 = sbr[2 * lane], ar1 = sbr[2 * lane + 1];

#pragma unroll 4
    for (int k2 = 0; k2 < 32; ++k2) {
        float xa = __shfl_sync(0xFFFFFFFFu, xv.x, k2);
        float xb = __shfl_sync(0xFFFFFFFFu, xv.y, k2);
        float fa = __shfl_sync(0xFFFFFFFFu, nf0, k2);
        float fb = __shfl_sync(0xFFFFFFFFu, nf1, k2);
        float ra = __shfl_sync(0xFFFFFFFFu, nr0, k2);
        float rb = __shfl_sync(0xFFFFFFFFu, nr1, k2);
        int ka = 2 * k2, kb = 2 * k2 + 1;
        float2 w;
        w = *(const float2*)(sWsf + ka * 64 + 2 * lane); af0 = fmaf(xa, w.x, af0); af1 = fmaf(xa, w.y, af1);
        w = *(const float2*)(sWsf + kb * 64 + 2 * lane); af0 = fmaf(xb, w.x, af0); af1 = fmaf(xb, w.y, af1);
        w = *(const float2*)(sWnf + ka * 64 + 2 * lane); af0 = fmaf(fa, w.x, af0); af1 = fmaf(fa, w.y, af1);
        w = *(const float2*)(sWnf + kb * 64 + 2 * lane); af0 = fmaf(fb, w.x, af0); af1 = fmaf(fb, w.y, af1);
        w = *(const float2*)(sWsr + ka * 64 + 2 * lane); ar0 = fmaf(xa, w.x, ar0); ar1 = fmaf(xa, w.y, ar1);
        w = *(const float2*)(sWsr + kb * 64 + 2 * lane); ar0 = fmaf(xb, w.x, ar0); ar1 = fmaf(xb, w.y, ar1);
        w = *(const float2*)(sWnr + ka * 64 + 2 * lane); ar0 = fmaf(ra, w.x, ar0); ar1 = fmaf(ra, w.y, ar1);
        w = *(const float2*)(sWnr + kb * 64 + 2 * lane); ar0 = fmaf(rb, w.x, ar0); ar1 = fmaf(rb, w.y, ar1);
    }
    float u0 = xv.x + fmaxf(af0, 0.f) + fmaxf(ar0, 0.f);
    float u1 = xv.y + fmaxf(af1, 0.f) + fmaxf(ar1, 0.f);
    float ss = u0 * u0 + u1 * u1;
#pragma unroll
    for (int o = 16; o > 0; o >>= 1) ss += __shfl_xor_sync(0xFFFFFFFFu, ss, o);
    float rinv = 1.0f / sqrtf(ss);
    ((float2*)(out + (long long)i * HID))[lane] = make_float2(u0 * rinv, u1 * rinv);
}

// ---------------- launch ----------------------------------------------------
extern "C" void kernel_launch(void* const* d_in, const int* in_sizes, int n_in,
                              void* d_out, int out_size) {
    const float* text = (const float*)d_in[0];
    const float* w    = (const float*)d_in[1];
    const float* Wenc = (const float*)d_in[2];
    const float* benc = (const float*)d_in[3];
    const float* Wsf  = (const float*)d_in[4];
    const float* Wnf  = (const float*)d_in[5];
    const float* bf   = (const float*)d_in[6];
    const float* Wsr  = (const float*)d_in[7];
    const float* Wnr  = (const float*)d_in[8];
    const float* br   = (const float*)d_in[9];
    const int*   src  = (const int*)d_in[10];
    const int*   dst  = (const int*)d_in[11];
    const int*   ids  = (const int*)d_in[12];
    float* out = (float*)d_out;

    const int UPD_SMEM   = (4 * 4096 + 48 * 132) * (int)sizeof(float);  // 90,880
    const int BATCH_SMEM = (4 * 4096 + 128) * (int)sizeof(float);       // 66,048
    const int ENC_SMEM   = (2 * 32 * SA_S + 2 * 32 * SW_S) * (int)sizeof(float); // 53,248

    static cudaStream_t s2 = 0, s3 = 0, s4 = 0;
    static cudaEvent_t evFork = 0, evEncA = 0, evEncB = 0, evZero = 0, evMark = 0, evFront = 0;
    if (s2 == 0) {
        cudaStreamCreateWithFlags(&s2, cudaStreamNonBlocking);
        cudaStreamCreateWithFlags(&s3, cudaStreamNonBlocking);
        cudaStreamCreateWithFlags(&s4, cudaStreamNonBlocking);
        cudaEventCreateWithFlags(&evFork,  cudaEventDisableTiming);
        cudaEventCreateWithFlags(&evEncA,  cudaEventDisableTiming);
        cudaEventCreateWithFlags(&evEncB,  cudaEventDisableTiming);
        cudaEventCreateWithFlags(&evZero,  cudaEventDisableTiming);
        cudaEventCreateWithFlags(&evMark,  cudaEventDisableTiming);
        cudaEventCreateWithFlags(&evFront, cudaEventDisableTiming);
        cudaFuncSetAttribute(k_updF,   cudaFuncAttributeMaxDynamicSharedMemorySize, UPD_SMEM);
        cudaFuncSetAttribute(k_batch,  cudaFuncAttributeMaxDynamicSharedMemorySize, BATCH_SMEM);
        cudaFuncSetAttribute(k_encMMA, cudaFuncAttributeMaxDynamicSharedMemorySize, ENC_SMEM);
    }

    // encoder fork: MMA path on s2 (rows [0, ENC_SPLIT)),
    //               FMA2 path on s4 (rows [ENC_SPLIT, NN)) — disjoint pipes.
    cudaEventRecord(evFork, 0);
    cudaStreamWaitEvent(s2, evFork, 0);
    cudaStreamWaitEvent(s4, evFork, 0);
    k_encMMA<<<ENC_SPLIT / 128, 128, ENC_SMEM, s2>>>(text, Wenc, benc, 0, ENC_SPLIT);
    cudaEventRecord(evEncA, s2);
    k_enc2<<<(NN - ENC_SPLIT + 127) / 128, 128, 0, s4>>>(text, Wenc, benc, ENC_SPLIT, NN);
    cudaEventRecord(evEncB, s4);

    // main: zero, then CSR hist/scans
    k_zero<<<(NN + 255) / 256, 256>>>();
    cudaEventRecord(evZero, 0);

    // branch: frontier from raw edge list (needs only zeroed flags/bitmaps)
    cudaStreamWaitEvent(s3, evZero, 0);
    k_bset<<<1, NBATCH, 0, s3>>>(ids);
    k_markE<<<1024, 256, 0, s3>>>(src, dst);
    cudaEventRecord(evMark, s3);
    k_scanA2<<<NB_SCAN, 1024, 0, s3>>>();
    k_scanB2<<<1, 128, 0, s3>>>();
    k_compact<<<(NN + 255) / 256, 256, 0, s3>>>();
    cudaEventRecord(evFront, s3);

    // main CSR chain (fill gated on frontier bitmap)
    k_hist<<<1024, 256>>>(src, dst);
    k_scanA01<<<2 * NB_SCAN, 1024>>>();
    k_scanB01<<<2, 128>>>();
    k_scanC01<<<(2 * NN + 255) / 256, 256>>>();
    cudaStreamWaitEvent(0, evMark, 0);       // fill needs d_fbit
    k_fill<<<1024, 256>>>(src, dst, w);

    // join all branches before layer-0
    cudaStreamWaitEvent(0, evEncA, 0);
    cudaStreamWaitEvent(0, evEncB, 0);
    cudaStreamWaitEvent(0, evFront, 0);

    // layer 0 restricted to frontier: both directions in ONE launch
    k_aggF2<<<2 * ((NN + 7) / 8), 256>>>();
    k_updF<<<(NN + 127) / 128, 256, UPD_SMEM>>>(Wsf, Wnf, bf, Wsr, Wnr, br);

    // layer 1: only at the 1024 output nodes (fused agg+update+norm)
    k_batch<<<NBATCH / 8, 256, BATCH_SMEM>>>(ids,
        Wsf + 4096, Wnf + 4096, bf + 64,
        Wsr + 4096, Wnr + 4096, br + 64, out);
}

// round 13
// speedup vs baseline: 1.5681x; 1.2299x over previous
#include <cuda_runtime.h>
#include <cstdint>

#define NN   100000
#define NE   1600000
#define HID  64
#define TXT  384
#define NBATCH 1024
#define NB_SCAN 98            // ceil(NN/1024)
#define NBW  3125             // ceil(NN/32) bitmap words

// ---------------- scratch (device globals; no allocation allowed) ----------
__device__ int      d_row_f[NN + 1];
__device__ int      d_row_r[NN + 1];
__device__ int      d_cur_f[NN];
__device__ int      d_cur_r[NN];
__device__ int      d_flag[NN];
__device__ int      d_fpos[NN];
__device__ int      d_front[NN];
__device__ int      d_cnt;
__device__ unsigned d_bbit[NBW];      // batch bitmap
__device__ unsigned d_fbit[NBW];      // frontier bitmap
__device__ int2     d_e_f[NE];        // (neighbor, weight-bits) fused
__device__ int2     d_e_r[NE];
__device__ float    d_x [NN * HID];
__device__ float    d_nf[NN * HID];
__device__ float    d_nr[NN * HID];
__device__ int      d_bsum[384];

// ---------------- f32x2 helpers ---------------------------------------------
__device__ __forceinline__ unsigned long long pack2(float lo, float hi) {
    unsigned long long r;
    asm("mov.b64 %0, {%1, %2};" : "=l"(r) : "f"(lo), "f"(hi));
    return r;
}
__device__ __forceinline__ void unpack2(unsigned long long v, float& lo, float& hi) {
    asm("mov.b64 {%0, %1}, %2;" : "=f"(lo), "=f"(hi) : "l"(v));
}
__device__ __forceinline__ void fma2(unsigned long long& d,
                                     unsigned long long a, unsigned long long b) {
    asm("fma.rn.f32x2 %0, %1, %2, %0;" : "+l"(d) : "l"(a), "l"(b));
}
__device__ __forceinline__ bool getbit(const unsigned* bm, int v) {
    return (bm[v >> 5] >> (v & 31)) & 1u;
}

// ---------------- bf16 mma helpers ------------------------------------------
// pack two f32 into bf16x2: lo half = first arg, hi half = second arg
__device__ __forceinline__ uint32_t pack_bf(float lo, float hi) {
    uint32_t r;
    asm("cvt.rn.bf16x2.f32 %0, %1, %2;" : "=r"(r) : "f"(hi), "f"(lo));
    return r;
}
__device__ __forceinline__ float bflo_f(uint32_t w) {
    return __int_as_float(w << 16);
}
__device__ __forceinline__ float bfhi_f(uint32_t w) {
    return __int_as_float(w & 0xFFFF0000u);
}
__device__ __forceinline__ void mma_bf16(float* d, const uint32_t* a,
                                         const uint32_t* b) {
    asm volatile(
        "mma.sync.aligned.m16n8k16.row.col.f32.bf16.bf16.f32 "
        "{%0,%1,%2,%3}, {%4,%5,%6,%7}, {%8,%9}, {%0,%1,%2,%3};"
        : "+f"(d[0]), "+f"(d[1]), "+f"(d[2]), "+f"(d[3])
        : "r"(a[0]), "r"(a[1]), "r"(a[2]), "r"(a[3]), "r"(b[0]), "r"(b[1]));
}

// ---------------- CSR construction -----------------------------------------
__global__ void k_zero() {
    int i = blockIdx.x * blockDim.x + threadIdx.x;
    if (i < NN) { d_cur_f[i] = 0; d_cur_r[i] = 0; d_flag[i] = 0; }
    if (i < NBW) { d_bbit[i] = 0; d_fbit[i] = 0; }
}

__global__ void k_bset(const int* __restrict__ ids) {
    int v = ids[threadIdx.x];
    atomicOr(&d_bbit[v >> 5], 1u << (v & 31));
    atomicOr(&d_fbit[v >> 5], 1u << (v & 31));
    d_flag[v] = 1;
}

__global__ void k_markE(const int* __restrict__ src, const int* __restrict__ dst) {
    for (int e = blockIdx.x * blockDim.x + threadIdx.x; e < NE;
         e += gridDim.x * blockDim.x) {
        int s = src[e], d = dst[e];
        if (getbit(d_bbit, d)) { d_flag[s] = 1; atomicOr(&d_fbit[s >> 5], 1u << (s & 31)); }
        if (getbit(d_bbit, s)) { d_flag[d] = 1; atomicOr(&d_fbit[d >> 5], 1u << (d & 31)); }
    }
}

__global__ void k_hist(const int* __restrict__ src, const int* __restrict__ dst) {
    for (int e = blockIdx.x * blockDim.x + threadIdx.x; e < NE;
         e += gridDim.x * blockDim.x) {
        atomicAdd(&d_cur_f[dst[e]], 1);
        atomicAdd(&d_cur_r[src[e]], 1);
    }
}

__device__ __forceinline__ int wscan(int x, int lane) {
#pragma unroll
    for (int o = 1; o < 32; o <<= 1) {
        int t = __shfl_up_sync(0xFFFFFFFFu, x, o);
        if (lane >= o) x += t;
    }
    return x;
}

__device__ __forceinline__ void scanA_body(const int* cnt, int* out, int which, int blk) {
    __shared__ int ws[32];
    int t = threadIdx.x, lane = t & 31, wid = t >> 5;
    int i = blk * 1024 + t;
    int v = (i < NN) ? cnt[i] : 0;
    int x = wscan(v, lane);
    if (lane == 31) ws[wid] = x;
    __syncthreads();
    if (wid == 0) ws[lane] = wscan(ws[lane], lane);
    __syncthreads();
    int off = wid ? ws[wid - 1] : 0;
    int incl = x + off;
    if (i < NN) out[i] = incl - v;
    if (t == 1023) d_bsum[which * 128 + blk] = incl;
}

__global__ void k_scanA01() {
    int which = blockIdx.x / NB_SCAN;
    int blk   = blockIdx.x % NB_SCAN;
    scanA_body(which ? d_cur_r : d_cur_f, which ? d_row_r : d_row_f, which, blk);
}
__global__ void k_scanA2() {
    scanA_body(d_flag, d_fpos, 2, blockIdx.x);
}

__device__ __forceinline__ void scanB_body(int which) {
    __shared__ int ws[4];
    int t = threadIdx.x, lane = t & 31, wid = t >> 5;
    int v = (t < NB_SCAN) ? d_bsum[which * 128 + t] : 0;
    int x = wscan(v, lane);
    if (lane == 31) ws[wid] = x;
    __syncthreads();
    int off = 0;
    for (int w2 = 0; w2 < wid; ++w2) off += ws[w2];
    d_bsum[which * 128 + t] = x + off - v;   // exclusive
}
__global__ void k_scanB01() { scanB_body(blockIdx.x); }     // grid=2
__global__ void k_scanB2()  { scanB_body(2); }              // grid=1

__global__ void k_scanC01() {
    int g = blockIdx.x * blockDim.x + threadIdx.x;
    int which = (g >= NN) ? 1 : 0;
    int i = g - which * NN;
    if (i >= NN) return;
    int* row = which ? d_row_r : d_row_f;
    int* cur = which ? d_cur_r : d_cur_f;
    int r = row[i] + d_bsum[which * 128 + (i >> 10)];
    row[i] = r;
    cur[i] = r;
    if (i == 0) row[NN] = NE;
}

// fill gated on frontier bitmap
__global__ void k_fill(const int* __restrict__ src, const int* __restrict__ dst,
                       const float* __restrict__ w) {
    for (int e = blockIdx.x * blockDim.x + threadIdx.x; e < NE;
         e += gridDim.x * blockDim.x) {
        int s = src[e], d = dst[e];
        int wb = __float_as_int(w[e]);
        if (getbit(d_fbit, d)) {
            int p = atomicAdd(&d_cur_f[d], 1);
            d_e_f[p] = make_int2(s, wb);
        }
        if (getbit(d_fbit, s)) {
            int q = atomicAdd(&d_cur_r[s], 1);
            d_e_r[q] = make_int2(d, wb);
        }
    }
}

__global__ void k_compact() {
    int i = blockIdx.x * blockDim.x + threadIdx.x;
    if (i >= NN) return;
    int pos = d_fpos[i] + d_bsum[2 * 128 + (i >> 10)];
    int f = d_flag[i];
    if (f) d_front[pos] = i;
    if (i == NN - 1) d_cnt = pos + f;
}

// ---------------- encoder: x = text @ W_enc + b_enc (bf16 m16n8k16) --------
// 128x64 block tile, 128 threads (4 warps), each warp 32x64 via 2x8 tiles.
// hi/lo bf16 split (3 mma per tile) -> ~1e-5 accuracy. K=384 in 12 chunks.
// Packed bf16x2 words, row stride 20 words -> conflict-free fragment loads.
#define AW 20
__global__ __launch_bounds__(128)
void k_encBF(const float* __restrict__ A, const float* __restrict__ W,
             const float* __restrict__ b) {
    __shared__ uint32_t sAh[128 * AW];
    __shared__ uint32_t sAl[128 * AW];
    __shared__ uint32_t sBh[64 * AW];
    __shared__ uint32_t sBl[64 * AW];

    int tid  = threadIdx.x;
    int warp = tid >> 5, lane = tid & 31;
    int g = lane >> 2, tig = lane & 3;
    int row0 = blockIdx.x * 128;

    float acc[2][8][4];
#pragma unroll
    for (int mt = 0; mt < 2; ++mt)
#pragma unroll
        for (int nt = 0; nt < 8; ++nt)
#pragma unroll
            for (int q = 0; q < 4; ++q) acc[mt][nt][q] = 0.f;

    for (int kc = 0; kc < 12; ++kc) {
        // stage A chunk [128 rows][32 k] -> packed bf16x2 hi/lo
#pragma unroll
        for (int p = 0; p < 8; ++p) {
            int lin = tid + p * 128;
            int r = lin >> 3, kq = lin & 7;
            int gr = row0 + r; if (gr >= NN) gr = NN - 1;
            float4 v = *(const float4*)(A + (long long)gr * TXT + kc * 32 + kq * 4);
            uint32_t hw0 = pack_bf(v.x, v.y);
            uint32_t hw1 = pack_bf(v.z, v.w);
            uint32_t lw0 = pack_bf(v.x - bflo_f(hw0), v.y - bfhi_f(hw0));
            uint32_t lw1 = pack_bf(v.z - bflo_f(hw1), v.w - bfhi_f(hw1));
            int base = r * AW + kq * 2;
            sAh[base]     = hw0; sAh[base + 1] = hw1;
            sAl[base]     = lw0; sAl[base + 1] = lw1;
        }
        // stage W chunk [32 k][64 n] -> sB[n][k-pair] packed bf16x2 hi/lo
#pragma unroll
        for (int p = 0; p < 8; ++p) {
            int lin = tid + p * 128;          // 0..1023
            int n = lin & 63, kp = lin >> 6;  // kp 0..15
            int k = kc * 32 + 2 * kp;
            float f0 = W[(long long)k * HID + n];
            float f1 = W[(long long)(k + 1) * HID + n];
            uint32_t hw = pack_bf(f0, f1);
            uint32_t lw = pack_bf(f0 - bflo_f(hw), f1 - bfhi_f(hw));
            sBh[n * AW + kp] = hw;
            sBl[n * AW + kp] = lw;
        }
        __syncthreads();

#pragma unroll
        for (int s = 0; s < 2; ++s) {          // two K=16 steps per chunk
            int woff = s * 8 + tig;
            uint32_t ah[2][4], al[2][4];
#pragma unroll
            for (int mt = 0; mt < 2; ++mt) {
                int R = warp * 32 + mt * 16 + g;
                ah[mt][0] = sAh[R * AW + woff];
                ah[mt][1] = sAh[(R + 8) * AW + woff];
                ah[mt][2] = sAh[R * AW + woff + 4];
                ah[mt][3] = sAh[(R + 8) * AW + woff + 4];
                al[mt][0] = sAl[R * AW + woff];
                al[mt][1] = sAl[(R + 8) * AW + woff];
                al[mt][2] = sAl[R * AW + woff + 4];
                al[mt][3] = sAl[(R + 8) * AW + woff + 4];
            }
#pragma unroll
            for (int nt = 0; nt < 8; ++nt) {
                int n = nt * 8 + g;
                uint32_t bh[2], bl[2];
                bh[0] = sBh[n * AW + woff];
                bh[1] = sBh[n * AW + woff + 4];
                bl[0] = sBl[n * AW + woff];
                bl[1] = sBl[n * AW + woff + 4];
#pragma unroll
                for (int mt = 0; mt < 2; ++mt) {
                    mma_bf16(acc[mt][nt], ah[mt], bh);
                    mma_bf16(acc[mt][nt], ah[mt], bl);
                    mma_bf16(acc[mt][nt], al[mt], bh);
                }
            }
        }
        __syncthreads();
    }

    // epilogue: D + bias -> d_x (C layout identical to tf32 m16n8k8)
#pragma unroll
    for (int mt = 0; mt < 2; ++mt) {
#pragma unroll
        for (int nt = 0; nt < 8; ++nt) {
            int c = nt * 8 + 2 * tig;
            float2 bb = *(const float2*)(b + c);
            int r0 = row0 + warp * 32 + mt * 16 + g;
            if (r0 < NN) {
                float2 o = make_float2(acc[mt][nt][0] + bb.x,
                                       acc[mt][nt][1] + bb.y);
                *(float2*)(d_x + (long long)r0 * HID + c) = o;
            }
            int r1 = r0 + 8;
            if (r1 < NN) {
                float2 o = make_float2(acc[mt][nt][2] + bb.x,
                                       acc[mt][nt][3] + bb.y);
                *(float2*)(d_x + (long long)r1 * HID + c) = o;
            }
        }
    }
}

// ---------------- frontier aggregation, BOTH directions in one launch ------
__global__ void k_aggF2() {
    int M = d_cnt;
    int lane = threadIdx.x & 31;
    int w = blockIdx.x * (blockDim.x >> 5) + (threadIdx.x >> 5);
    int which = (w >= NN) ? 1 : 0;
    int idx = w - which * NN;
    if (idx >= M) return;
    int v = d_front[idx];
    const int*  row = which ? d_row_r : d_row_f;
    const int2* enb = which ? d_e_r   : d_e_f;
    float*      out = which ? d_nr    : d_nf;

    int beg = row[v], end = row[v + 1];
    float a0 = 0.f, a1 = 0.f;
#pragma unroll 4
    for (int e = beg; e < end; ++e) {
        int2 ed = enb[e];
        float wv = __int_as_float(ed.y);
        float2 xv = *(const float2*)(d_x + (long long)ed.x * HID + 2 * lane);
        a0 = fmaf(wv, xv.x, a0);
        a1 = fmaf(wv, xv.y, a1);
    }
    float inv = (end > beg) ? 1.0f / (float)(end - beg) : 0.f;
    ((float2*)(out + (long long)v * HID))[lane] = make_float2(a0 * inv, a1 * inv);
}

// ---------------- layer-0 update at frontier rows only ---------------------
__global__ __launch_bounds__(256, 2)
void k_updF(const float* __restrict__ Wsf, const float* __restrict__ Wnf,
            const float* __restrict__ bf,
            const float* __restrict__ Wsr, const float* __restrict__ Wnr,
            const float* __restrict__ br) {
    int M = d_cnt;
    int row0 = blockIdx.x * 128;
    if (row0 >= M) return;

    extern __shared__ float sm[];
    float (*sW)[64][64] = (float (*)[64][64])sm;        // 4 x 64 x 64 = 64KB
    float (*sX)[132] = (float (*)[132])(sm + 4 * 4096);
    float (*sF)[132] = (float (*)[132])(sm + 4 * 4096 + 16 * 132);
    float (*sR)[132] = (float (*)[132])(sm + 4 * 4096 + 32 * 132);

    int tid = threadIdx.x;
    int cb = tid & 15;
    int rb = tid >> 4;
    int c0 = cb * 4, r0 = rb * 8;

#pragma unroll
    for (int p = 0; p < 16; ++p) {
        int lin = (tid + p * 256) * 4;
        int m = lin >> 12, rem = lin & 4095;
        const float* srcw = (m == 0) ? Wsf : (m == 1) ? Wnf : (m == 2) ? Wsr : Wnr;
        *(float4*)&sW[m][rem >> 6][rem & 63] = *(const float4*)(srcw + rem);
    }

    unsigned long long accf[4][4], accr[4][4];
#pragma unroll
    for (int c = 0; c < 4; ++c) {
        float bvf = __ldg(bf + c0 + c), bvr = __ldg(br + c0 + c);
        unsigned long long pf = pack2(bvf, bvf), pr = pack2(bvr, bvr);
#pragma unroll
        for (int rp = 0; rp < 4; ++rp) { accf[rp][c] = pf; accr[rp][c] = pr; }
    }

    for (int kc = 0; kc < HID; kc += 16) {
        __syncthreads();
#pragma unroll
        for (int p = 0; p < 2; ++p) {
            int lin = tid + p * 256;
            int r = lin >> 2, c4 = (lin & 3) * 4;
            int gi = row0 + r;
            int node = d_front[(gi < M) ? gi : (M - 1)];
            long long base = (long long)node * HID + kc + c4;
            float4 vx = *(const float4*)(d_x + base);
            float4 vf = *(const float4*)(d_nf + base);
            float4 vr = *(const float4*)(d_nr + base);
            sX[c4 + 0][r] = vx.x; sX[c4 + 1][r] = vx.y; sX[c4 + 2][r] = vx.z; sX[c4 + 3][r] = vx.w;
            sF[c4 + 0][r] = vf.x; sF[c4 + 1][r] = vf.y; sF[c4 + 2][r] = vf.z; sF[c4 + 3][r] = vf.w;
            sR[c4 + 0][r] = vr.x; sR[c4 + 1][r] = vr.y; sR[c4 + 2][r] = vr.z; sR[c4 + 3][r] = vr.w;
        }
        __syncthreads();

#pragma unroll
        for (int k = 0; k < 16; ++k) {
            int gk = kc + k;
            ulonglong2 xA = *(const ulonglong2*)&sX[k][r0];
            ulonglong2 xB = *(const ulonglong2*)&sX[k][r0 + 4];
            ulonglong2 fA = *(const ulonglong2*)&sF[k][r0];
            ulonglong2 fB = *(const ulonglong2*)&sF[k][r0 + 4];
            ulonglong2 rA = *(const ulonglong2*)&sR[k][r0];
            ulonglong2 rB = *(const ulonglong2*)&sR[k][r0 + 4];
            unsigned long long x2[4] = { xA.x, xA.y, xB.x, xB.y };
            unsigned long long f2[4] = { fA.x, fA.y, fB.x, fB.y };
            unsigned long long r2[4] = { rA.x, rA.y, rB.x, rB.y };
            float4 wsf = *(const float4*)&sW[0][gk][c0];
            float4 wnf = *(const float4*)&sW[1][gk][c0];
            float4 wsr = *(const float4*)&sW[2][gk][c0];
            float4 wnr = *(const float4*)&sW[3][gk][c0];
            float vsf[4] = { wsf.x, wsf.y, wsf.z, wsf.w };
            float vnf[4] = { wnf.x, wnf.y, wnf.z, wnf.w };
            float vsr[4] = { wsr.x, wsr.y, wsr.z, wsr.w };
            float vnr[4] = { wnr.x, wnr.y, wnr.z, wnr.w };
#pragma unroll
            for (int c = 0; c < 4; ++c) {
                unsigned long long wsf2 = pack2(vsf[c], vsf[c]);
                unsigned long long wnf2 = pack2(vnf[c], vnf[c]);
                unsigned long long wsr2 = pack2(vsr[c], vsr[c]);
                unsigned long long wnr2 = pack2(vnr[c], vnr[c]);
#pragma unroll
                for (int rp = 0; rp < 4; ++rp) {
                    fma2(accf[rp][c], x2[rp], wsf2);
                    fma2(accf[rp][c], f2[rp], wnf2);
                    fma2(accr[rp][c], x2[rp], wsr2);
                    fma2(accr[rp][c], r2[rp], wnr2);
                }
            }
        }
    }

#pragma unroll
    for (int rp = 0; rp < 4; ++rp) {
#pragma unroll
        for (int h = 0; h < 2; ++h) {
            int gi = row0 + r0 + 2 * rp + h;
            if (gi >= M) continue;
            int node = d_front[gi];
            float* xp = d_x + (long long)node * HID + c0;
            float4 xv = *(const float4*)xp;
            float vf[4], vr[4];
#pragma unroll
            for (int c = 0; c < 4; ++c) {
                float lo, hi;
                unpack2(accf[rp][c], lo, hi); vf[c] = h ? hi : lo;
                unpack2(accr[rp][c], lo, hi); vr[c] = h ? hi : lo;
            }
            xv.x += fmaxf(vf[0], 0.f) + fmaxf(vr[0], 0.f);
            xv.y += fmaxf(vf[1], 0.f) + fmaxf(vr[1], 0.f);
            xv.z += fmaxf(vf[2], 0.f) + fmaxf(vr[2], 0.f);
            xv.w += fmaxf(vf[3], 0.f) + fmaxf(vr[3], 0.f);
            *(float4*)xp = xv;
        }
    }
}

// ---------------- layer 2 fused, batch nodes only + L2-normalize -----------
__global__ void k_batch(const int* __restrict__ ids,
                        const float* __restrict__ Wsf, const float* __restrict__ Wnf,
                        const float* __restrict__ bf,
                        const float* __restrict__ Wsr, const float* __restrict__ Wnr,
                        const float* __restrict__ br,
                        float* __restrict__ out) {
    extern __shared__ float sm[];
    float *sWsf = sm, *sWnf = sm + 4096, *sWsr = sm + 8192, *sWnr = sm + 12288;
    float *sbf  = sm + 16384, *sbr = sm + 16448;
    for (int i = threadIdx.x; i < 4096; i += blockDim.x) {
        sWsf[i] = Wsf[i]; sWnf[i] = Wnf[i]; sWsr[i] = Wsr[i]; sWnr[i] = Wnr[i];
    }
    if (threadIdx.x < 64) { sbf[threadIdx.x] = bf[threadIdx.x]; sbr[threadIdx.x] = br[threadIdx.x]; }
    __syncthreads();

    int lane = threadIdx.x & 31;
    int i = blockIdx.x * (blockDim.x >> 5) + (threadIdx.x >> 5);
    if (i >= NBATCH) return;
    int v = ids[i];

    float nf0 = 0.f, nf1 = 0.f;
    int beg = d_row_f[v], end = d_row_f[v + 1];
#pragma unroll 4
    for (int e = beg; e < end; ++e) {
        int2 ed = d_e_f[e];
        float wv = __int_as_float(ed.y);
        float2 xv = *(const float2*)(d_x + (long long)ed.x * HID + 2 * lane);
        nf0 = fmaf(wv, xv.x, nf0); nf1 = fmaf(wv, xv.y, nf1);
    }
    float inv = (end > beg) ? 1.0f / (float)(end - beg) : 0.f;
    nf0 *= inv; nf1 *= inv;

    float nr0 = 0.f, nr1 = 0.f;
    beg = d_row_r[v]; end = d_row_r[v + 1];
#pragma unroll 4
    for (int e = beg; e < end; ++e) {
        int2 ed = d_e_r[e];
        float wv = __int_as_float(ed.y);
        float2 xv = *(const float2*)(d_x + (long long)ed.x * HID + 2 * lane);
        nr0 = fmaf(wv, xv.x, nr0); nr1 = fmaf(wv, xv.y, nr1);
    }
    inv = (end > beg) ? 1.0f / (float)(end - beg) : 0.f;
    nr0 *= inv; nr1 *= inv;

    float2 xv = *(const float2*)(d_x + (long long)v * HID + 2 * lane);
    float af0 = sbf[2 * lane], af1 = sbf[2 * lane + 1];
    float ar0 = sbr[2 * lane], ar1 = sbr[2 * lane + 1];

#pragma unroll 4
    for (int k2 = 0; k2 < 32; ++k2) {
        float xa = __shfl_sync(0xFFFFFFFFu, xv.x, k2);
        float xb = __shfl_sync(0xFFFFFFFFu, xv.y, k2);
        float fa = __shfl_sync(0xFFFFFFFFu, nf0, k2);
        float fb = __shfl_sync(0xFFFFFFFFu, nf1, k2);
        float ra = __shfl_sync(0xFFFFFFFFu, nr0, k2);
        float rb = __shfl_sync(0xFFFFFFFFu, nr1, k2);
        int ka = 2 * k2, kb = 2 * k2 + 1;
        float2 w;
        w = *(const float2*)(sWsf + ka * 64 + 2 * lane); af0 = fmaf(xa, w.x, af0); af1 = fmaf(xa, w.y, af1);
        w = *(const float2*)(sWsf + kb * 64 + 2 * lane); af0 = fmaf(xb, w.x, af0); af1 = fmaf(xb, w.y, af1);
        w = *(const float2*)(sWnf + ka * 64 + 2 * lane); af0 = fmaf(fa, w.x, af0); af1 = fmaf(fa, w.y, af1);
        w = *(const float2*)(sWnf + kb * 64 + 2 * lane); af0 = fmaf(fb, w.x, af0); af1 = fmaf(fb, w.y, af1);
        w = *(const float2*)(sWsr + ka * 64 + 2 * lane); ar0 = fmaf(xa, w.x, ar0); ar1 = fmaf(xa, w.y, ar1);
        w = *(const float2*)(sWsr + kb * 64 + 2 * lane); ar0 = fmaf(xb, w.x, ar0); ar1 = fmaf(xb, w.y, ar1);
        w = *(const float2*)(sWnr + ka * 64 + 2 * lane); ar0 = fmaf(ra, w.x, ar0); ar1 = fmaf(ra, w.y, ar1);
        w = *(const float2*)(sWnr + kb * 64 + 2 * lane); ar0 = fmaf(rb, w.x, ar0); ar1 = fmaf(rb, w.y, ar1);
    }
    float u0 = xv.x + fmaxf(af0, 0.f) + fmaxf(ar0, 0.f);
    float u1 = xv.y + fmaxf(af1, 0.f) + fmaxf(ar1, 0.f);
    float ss = u0 * u0 + u1 * u1;
#pragma unroll
    for (int o = 16; o > 0; o >>= 1) ss += __shfl_xor_sync(0xFFFFFFFFu, ss, o);
    float rinv = 1.0f / sqrtf(ss);
    ((float2*)(out + (long long)i * HID))[lane] = make_float2(u0 * rinv, u1 * rinv);
}

// ---------------- launch ----------------------------------------------------
extern "C" void kernel_launch(void* const* d_in, const int* in_sizes, int n_in,
                              void* d_out, int out_size) {
    const float* text = (const float*)d_in[0];
    const float* w    = (const float*)d_in[1];
    const float* Wenc = (const float*)d_in[2];
    const float* benc = (const float*)d_in[3];
    const float* Wsf  = (const float*)d_in[4];
    const float* Wnf  = (const float*)d_in[5];
    const float* bf   = (const float*)d_in[6];
    const float* Wsr  = (const float*)d_in[7];
    const float* Wnr  = (const float*)d_in[8];
    const float* br   = (const float*)d_in[9];
    const int*   src  = (const int*)d_in[10];
    const int*   dst  = (const int*)d_in[11];
    const int*   ids  = (const int*)d_in[12];
    float* out = (float*)d_out;

    const int UPD_SMEM   = (4 * 4096 + 48 * 132) * (int)sizeof(float);  // 90,880
    const int BATCH_SMEM = (4 * 4096 + 128) * (int)sizeof(float);       // 66,048

    static cudaStream_t s2 = 0, s3 = 0;
    static cudaEvent_t evFork = 0, evEnc = 0, evZero = 0, evMark = 0, evFront = 0;
    if (s2 == 0) {
        cudaStreamCreateWithFlags(&s2, cudaStreamNonBlocking);
        cudaStreamCreateWithFlags(&s3, cudaStreamNonBlocking);
        cudaEventCreateWithFlags(&evFork,  cudaEventDisableTiming);
        cudaEventCreateWithFlags(&evEnc,   cudaEventDisableTiming);
        cudaEventCreateWithFlags(&evZero,  cudaEventDisableTiming);
        cudaEventCreateWithFlags(&evMark,  cudaEventDisableTiming);
        cudaEventCreateWithFlags(&evFront, cudaEventDisableTiming);
        cudaFuncSetAttribute(k_updF,  cudaFuncAttributeMaxDynamicSharedMemorySize, UPD_SMEM);
        cudaFuncSetAttribute(k_batch, cudaFuncAttributeMaxDynamicSharedMemorySize, BATCH_SMEM);
    }

    // branch 1: encoder (bf16 hi/lo MMA) — independent of everything
    cudaEventRecord(evFork, 0);
    cudaStreamWaitEvent(s2, evFork, 0);
    k_encBF<<<(NN + 127) / 128, 128, 0, s2>>>(text, Wenc, benc);
    cudaEventRecord(evEnc, s2);

    // main: zero, then CSR hist/scans
    k_zero<<<(NN + 255) / 256, 256>>>();
    cudaEventRecord(evZero, 0);

    // branch 2: frontier from raw edge list
    cudaStreamWaitEvent(s3, evZero, 0);
    k_bset<<<1, NBATCH, 0, s3>>>(ids);
    k_markE<<<1024, 256, 0, s3>>>(src, dst);
    cudaEventRecord(evMark, s3);
    k_scanA2<<<NB_SCAN, 1024, 0, s3>>>();
    k_scanB2<<<1, 128, 0, s3>>>();
    k_compact<<<(NN + 255) / 256, 256, 0, s3>>>();
    cudaEventRecord(evFront, s3);

    // main CSR chain (fill gated on frontier bitmap)
    k_hist<<<1024, 256>>>(src, dst);
    k_scanA01<<<2 * NB_SCAN, 1024>>>();
    k_scanB01<<<2, 128>>>();
    k_scanC01<<<(2 * NN + 255) / 256, 256>>>();
    cudaStreamWaitEvent(0, evMark, 0);       // fill needs d_fbit
    k_fill<<<1024, 256>>>(src, dst, w);

    // join all branches before layer-0
    cudaStreamWaitEvent(0, evEnc, 0);
    cudaStreamWaitEvent(0, evFront, 0);

    // layer 0 restricted to frontier: both directions in ONE launch
    k_aggF2<<<2 * ((NN + 7) / 8), 256>>>();
    k_updF<<<(NN + 127) / 128, 256, UPD_SMEM>>>(Wsf, Wnf, bf, Wsr, Wnr, br);

    // layer 1: only at the 1024 output nodes (fused agg+update+norm)
    k_batch<<<NBATCH / 8, 256, BATCH_SMEM>>>(ids,
        Wsf + 4096, Wnf + 4096, bf + 64,
        Wsr + 4096, Wnr + 4096, br + 64, out);
}